// round 4
// baseline (speedup 1.0000x reference)
#include <cuda_runtime.h>
#include <cuda_bf16.h>
#include <cstdint>
#include <math.h>

// CBTree B=4, L=9, d=256.
// C[p,n] = tanh( sum_k u[p,k] W(n,k) + bias[p,n] ),  u from child-combine.
// Split-bf16: A=[hi(u)|lo(u)] (K=1024), B=[hi(W)|lo(W)] (K=1024, row=n).
// 24 chunk passes of 64k: it 0-7 hi*hi, 8-15 lo*hi, 16-23 hi*lo — fp32 accum.
// GEMM epilogue fuses tanh + child-combine + hi/lo split for the next level.

#define D 256
#define KA 1024
#define ROWA 2048          // bytes per A row
#define ROWBB 2048         // bytes per B row
#define NIT 24
#define SROW 144           // smem row stride (128 data + 16 pad)
#define A_STAGE (128 * SROW)             // 18432
#define B_STAGE (256 * SROW)             // 36864
#define STAGE (A_STAGE + B_STAGE)        // 55296
#define HSTRIDE 257
#define SMEM_TOTAL (128 * HSTRIDE * 4)   // 131584 > 2*STAGE=110592

// ---------------- static device scratch ----------------
__device__ __nv_bfloat16 g_Acat0[16384 * 1024];  // 32 MB
__device__ __nv_bfloat16 g_Acat1[16384 * 1024];  // 32 MB
__device__ __nv_bfloat16 g_Bcat[256 * 1024];     // 512 KB

// ---------------- helpers ----------------
__device__ __forceinline__ uint32_t smem_u32(const void* p) {
    uint32_t a;
    asm("{ .reg .u64 t; cvta.to.shared.u64 t, %1; cvt.u32.u64 %0, t; }" : "=r"(a) : "l"(p));
    return a;
}
__device__ __forceinline__ void cp_async16(uint32_t dst, const void* src, bool pred) {
    int sz = pred ? 16 : 0;
    asm volatile("cp.async.cg.shared.global [%0], [%1], 16, %2;"
                 :: "r"(dst), "l"(src), "r"(sz));
}
#define CP_COMMIT() asm volatile("cp.async.commit_group;" ::: "memory")

__device__ __forceinline__ void ldm_x4(uint32_t* r, uint32_t addr) {
    asm volatile("ldmatrix.sync.aligned.m8n8.x4.shared.b16 {%0,%1,%2,%3}, [%4];"
                 : "=r"(r[0]), "=r"(r[1]), "=r"(r[2]), "=r"(r[3]) : "r"(addr));
}
__device__ __forceinline__ void mma_bf16(float* c, const uint32_t* a, uint32_t b0, uint32_t b1) {
    asm volatile("mma.sync.aligned.m16n8k16.row.col.f32.bf16.bf16.f32 "
                 "{%0,%1,%2,%3}, {%4,%5,%6,%7}, {%8,%9}, {%0,%1,%2,%3};"
                 : "+f"(c[0]), "+f"(c[1]), "+f"(c[2]), "+f"(c[3])
                 : "r"(a[0]), "r"(a[1]), "r"(a[2]), "r"(a[3]), "r"(b0), "r"(b1));
}
__device__ __forceinline__ void split_bf16(float v, __nv_bfloat16& hi, __nv_bfloat16& lo) {
    hi = __float2bfloat16_rn(v);
    lo = __float2bfloat16_rn(v - __bfloat162float(hi));
}

// ---------------- prep: Bcat = [hi(W) | lo(W)] per output row n ----------------
__global__ void prep_w_kernel(const float* __restrict__ Wl,
                              const float* __restrict__ Wr,
                              __nv_bfloat16* __restrict__ Bcat) {
    int idx = blockIdx.x * blockDim.x + threadIdx.x;   // 256*512
    if (idx >= D * 512) return;
    int n = idx >> 9;
    int k = idx & 511;
    float w = (k < D) ? Wl[n * D + k] : Wr[n * D + (k - D)];
    __nv_bfloat16 hi, lo;
    split_bf16(w, hi, lo);
    Bcat[(size_t)n * KA + k] = hi;
    Bcat[(size_t)n * KA + 512 + k] = lo;
}

// ---------------- leaf reduce: leaves (65536 x 256 fp32) -> Acat (16384 x 1024) ----------------
__global__ void leaf_reduce_kernel(const float* __restrict__ h,
                                   __nv_bfloat16* __restrict__ Acat,
                                   int n_par) {
    int idx = blockIdx.x * blockDim.x + threadIdx.x;
    if (idx >= n_par * 512) return;
    int p = idx >> 9;
    int k = idx & 511;
    const float* hp = h + (size_t)p * 1024;
    float u;
    if (k < D) {
        u = hp[k] + (2.0f / 3.0f) * hp[D + k] + (1.0f / 3.0f) * hp[2 * D + k];
    } else {
        int j = k - D;
        u = (1.0f / 3.0f) * hp[D + j] + (2.0f / 3.0f) * hp[2 * D + j] + hp[3 * D + j];
    }
    __nv_bfloat16 hi, lo;
    split_bf16(u, hi, lo);
    Acat[(size_t)p * KA + k] = hi;
    Acat[(size_t)p * KA + 512 + k] = lo;
}

// ---------------- GEMM 128xM tile x 256 N + tanh + fused combine ----------------
// 8 warps: 2(m) x 4(n), warp tile 64x64. K: 24 chunks of 64, double buffered.
__global__ void __launch_bounds__(256)
gemm_fused_kernel(const __nv_bfloat16* __restrict__ A,
                  const __nv_bfloat16* __restrict__ B,
                  const float* __restrict__ bias,
                  __nv_bfloat16* __restrict__ Anext,   // null on last level
                  float* __restrict__ outp,            // null except last level
                  int M) {
    extern __shared__ __align__(128) char smem[];
    const uint32_t sbase = smem_u32(smem);
    const int tid = threadIdx.x;
    const int wid = tid >> 5;
    const int lid = tid & 31;
    const int bm = blockIdx.x * 128;

    const char* Ab = (const char*)A;
    const char* Bb = (const char*)B;

    auto load_stage = [&](int buf, int it) {
        int aCh = (it < 16) ? it : it - 16;   // A: hi chunks reused for pass 3
        int bCh = (it < 8) ? it : it - 8;     // B: hi for 0-15, lo for 16-23
        uint32_t sA = sbase + buf * STAGE;
        uint32_t sB = sA + A_STAGE;
#pragma unroll
        for (int i = 0; i < 4; i++) {
            int id = i * 256 + tid;
            int r = id >> 3, c = id & 7;
            bool p = (bm + r) < M;
            const char* src = Ab + (size_t)(bm + r) * ROWA + aCh * 128 + c * 16;
            if (!p) src = Ab;
            cp_async16(sA + r * SROW + c * 16, src, p);
        }
#pragma unroll
        for (int i = 0; i < 8; i++) {
            int id = i * 256 + tid;
            int r = id >> 3, c = id & 7;
            const char* src = Bb + (size_t)r * ROWBB + bCh * 128 + c * 16;
            cp_async16(sB + r * SROW + c * 16, src, true);
        }
        CP_COMMIT();
    };

    float acc[4][8][4];
#pragma unroll
    for (int mf = 0; mf < 4; mf++)
#pragma unroll
        for (int nf = 0; nf < 8; nf++)
#pragma unroll
            for (int q = 0; q < 4; q++) acc[mf][nf][q] = 0.0f;

    const int wm = (wid & 1) * 64;
    const int wn = (wid >> 1) * 64;
    const uint32_t aOff = (uint32_t)(wm + (lid & 7) + ((lid & 8) ? 8 : 0)) * SROW +
                          ((lid & 16) ? 16 : 0);
    const uint32_t bOff = (uint32_t)(wn + (lid & 7) + ((lid & 16) ? 8 : 0)) * SROW +
                          ((lid & 8) ? 16 : 0);

    load_stage(0, 0);
    load_stage(1, 1);

    for (int it = 0; it < NIT; it++) {
        if (it + 2 < NIT) {
            asm volatile("cp.async.wait_group 1;" ::: "memory");
        } else {
            asm volatile("cp.async.wait_group 0;" ::: "memory");
        }
        __syncthreads();

        int buf = it & 1;
        uint32_t sA = sbase + buf * STAGE;
        uint32_t aAddr = sA + aOff;
        uint32_t bAddr = sA + A_STAGE + bOff;

#pragma unroll
        for (int kk = 0; kk < 4; kk++) {
            uint32_t af[4][4], bf[4][4];
#pragma unroll
            for (int mf = 0; mf < 4; mf++)
                ldm_x4(af[mf], aAddr + mf * 16 * SROW + kk * 32);
#pragma unroll
            for (int nf2 = 0; nf2 < 4; nf2++)
                ldm_x4(bf[nf2], bAddr + nf2 * 16 * SROW + kk * 32);
#pragma unroll
            for (int mf = 0; mf < 4; mf++)
#pragma unroll
                for (int nf2 = 0; nf2 < 4; nf2++) {
                    mma_bf16(acc[mf][nf2 * 2 + 0], af[mf], bf[nf2][0], bf[nf2][1]);
                    mma_bf16(acc[mf][nf2 * 2 + 1], af[mf], bf[nf2][2], bf[nf2][3]);
                }
        }
        __syncthreads();
        if (it + 2 < NIT) load_stage(buf, it + 2);
    }

    // ---- epilogue: tanh(acc + bias) -> smem h tile (and/or final output) ----
    __syncthreads();                     // everyone done with pipeline smem
    float* hs = (float*)smem;            // 128 x 256, stride HSTRIDE

#pragma unroll
    for (int mf = 0; mf < 4; mf++) {
#pragma unroll
        for (int half = 0; half < 2; half++) {
            int r = wm + mf * 16 + (lid >> 2) + half * 8;
            int grow = bm + r;
            if (grow >= M) continue;
            const float* brow = bias + (size_t)grow * D + wn;
            float* hrow = hs + r * HSTRIDE + wn;
#pragma unroll
            for (int nf = 0; nf < 8; nf++) {
                int col = nf * 8 + 2 * (lid & 3);
                float2 bv = *(const float2*)(brow + col);
                float x = tanhf(acc[mf][nf][half * 2 + 0] + bv.x);
                float y = tanhf(acc[mf][nf][half * 2 + 1] + bv.y);
                hrow[col] = x;
                hrow[col + 1] = y;
                if (outp) {
                    float* orow = outp + (size_t)grow * D + wn;
                    orow[col] = x;
                    orow[col + 1] = y;
                }
            }
        }
    }
    __syncthreads();

    // ---- fused child-combine -> Anext (hi|lo), 32 parents per CTA ----
    if (Anext) {
        int nPar = M >> 2;
        int p = tid >> 3;                // 0..31 local parent
        int g = tid & 7;
        int pg = (bm >> 2) + p;
        if (pg < nPar) {
            const float* h0 = hs + (4 * p + 0) * HSTRIDE;
            const float* h1 = hs + (4 * p + 1) * HSTRIDE;
            const float* h2 = hs + (4 * p + 2) * HSTRIDE;
            const float* h3 = hs + (4 * p + 3) * HSTRIDE;
            __nv_bfloat16* arow = Anext + (size_t)pg * KA;
#pragma unroll
            for (int i = 0; i < 8; i++) {
                int k0 = i * 64 + g * 8;
                float v[8];
                if (k0 < 256) {
#pragma unroll
                    for (int j = 0; j < 8; j++)
                        v[j] = h0[k0 + j] + (2.0f / 3.0f) * h1[k0 + j] +
                               (1.0f / 3.0f) * h2[k0 + j];
                } else {
                    int j0 = k0 - 256;
#pragma unroll
                    for (int j = 0; j < 8; j++)
                        v[j] = (1.0f / 3.0f) * h1[j0 + j] + (2.0f / 3.0f) * h2[j0 + j] +
                               h3[j0 + j];
                }
                __nv_bfloat16 hi[8], lo[8];
#pragma unroll
                for (int j = 0; j < 8; j++) split_bf16(v[j], hi[j], lo[j]);
                *(uint4*)(arow + k0) = *(const uint4*)hi;
                *(uint4*)(arow + 512 + k0) = *(const uint4*)lo;
            }
        }
    }
}

// ---------------- launcher ----------------
extern "C" void kernel_launch(void* const* d_in, const int* in_sizes, int n_in,
                              void* d_out, int out_size) {
    const float* vectors = (const float*)d_in[0];
    const float* Wl = (const float*)d_in[1];
    const float* Wr = (const float*)d_in[2];
    float* out = (float*)d_out;

    __nv_bfloat16 *Acat0, *Acat1, *Bcat;
    cudaGetSymbolAddress((void**)&Acat0, g_Acat0);
    cudaGetSymbolAddress((void**)&Acat1, g_Acat1);
    cudaGetSymbolAddress((void**)&Bcat, g_Bcat);

    cudaFuncSetAttribute(gemm_fused_kernel,
                         cudaFuncAttributeMaxDynamicSharedMemorySize, SMEM_TOTAL);

    prep_w_kernel<<<(D * 512 + 255) / 256, 256>>>(Wl, Wr, Bcat);

    static const int offs[9] = {0, 1, 5, 21, 85, 341, 1365, 5461, 21845};

    // Leaves -> Acat0 for level 7 (16384 parents)
    const float* leaves = vectors + (size_t)offs[8] * D;
    leaf_reduce_kernel<<<(16384 * 512 + 255) / 256, 256>>>(leaves, Acat0, 16384);

    __nv_bfloat16* Ain = Acat0;
    for (int l = 7; l >= 0; --l) {
        int M = 1 << (2 * l);
        __nv_bfloat16* Anext =
            (l > 0) ? ((Ain == Acat0) ? Acat1 : Acat0) : (__nv_bfloat16*)nullptr;
        float* outp = (l == 0) ? out : nullptr;
        const float* bias = vectors + (size_t)offs[l] * D;

        int grid = (M + 127) / 128;
        gemm_fused_kernel<<<grid, 256, SMEM_TOTAL>>>(Ain, Bcat, bias, Anext, outp, M);

        Ain = Anext;
    }
}

// round 5
// speedup vs baseline: 1.5488x; 1.5488x over previous
#include <cuda_runtime.h>
#include <cuda_bf16.h>
#include <cstdint>
#include <math.h>

// CBTree B=4, L=9, d=256.
// h_out[p,n] = tanh( sum_k u[p,k] W(n,k) + bias[p,n] ), u = child combine.
// Split-bf16: A=[hi(u)|lo(u)] (K=1024), B=[hi(W)|lo(W)] (K=1024).
// 24 chunk passes of 64: it 0-7 hi*hi, 8-15 lo*hi, 16-23 hi*lo (fp32 accum).
// GEMM tile 128x128, fused epilogue: tanh -> smem h -> combine -> Anext(hi|lo).

#define D 256
#define KA 1024
#define ROWA 2048        // bytes per A row
#define ROWBB 2048       // bytes per B row
#define NIT 24
#define SROW 144         // smem row stride bytes (128 data + 16 pad)
#define TILE_B (128 * SROW)        // 18432 per operand
#define STAGE (2 * TILE_B)         // 36864
#define NSTAGE 3
#define SMEM_TOTAL (NSTAGE * STAGE)  // 110592
#define HST 132                      // h tile stride (floats)

// ---------------- static device scratch ----------------
__device__ __nv_bfloat16 g_Acat0[16384 * 1024];  // 32 MB
__device__ __nv_bfloat16 g_Acat1[16384 * 1024];  // 32 MB
__device__ __nv_bfloat16 g_Bcat[256 * 1024];     // 512 KB

// ---------------- helpers ----------------
__device__ __forceinline__ uint32_t smem_u32(const void* p) {
    uint32_t a;
    asm("{ .reg .u64 t; cvta.to.shared.u64 t, %1; cvt.u32.u64 %0, t; }" : "=r"(a) : "l"(p));
    return a;
}
__device__ __forceinline__ void cp_async16(uint32_t dst, const void* src, bool pred) {
    int sz = pred ? 16 : 0;
    asm volatile("cp.async.cg.shared.global [%0], [%1], 16, %2;"
                 :: "r"(dst), "l"(src), "r"(sz));
}
#define CP_COMMIT() asm volatile("cp.async.commit_group;" ::: "memory")

__device__ __forceinline__ void ldm_x4(uint32_t* r, uint32_t addr) {
    asm volatile("ldmatrix.sync.aligned.m8n8.x4.shared.b16 {%0,%1,%2,%3}, [%4];"
                 : "=r"(r[0]), "=r"(r[1]), "=r"(r[2]), "=r"(r[3]) : "r"(addr));
}
__device__ __forceinline__ void mma_bf16(float* c, const uint32_t* a, uint32_t b0, uint32_t b1) {
    asm volatile("mma.sync.aligned.m16n8k16.row.col.f32.bf16.bf16.f32 "
                 "{%0,%1,%2,%3}, {%4,%5,%6,%7}, {%8,%9}, {%0,%1,%2,%3};"
                 : "+f"(c[0]), "+f"(c[1]), "+f"(c[2]), "+f"(c[3])
                 : "r"(a[0]), "r"(a[1]), "r"(a[2]), "r"(a[3]), "r"(b0), "r"(b1));
}
__device__ __forceinline__ void split_bf16(float v, __nv_bfloat16& hi, __nv_bfloat16& lo) {
    hi = __float2bfloat16_rn(v);
    lo = __float2bfloat16_rn(v - __bfloat162float(hi));
}

// ---------------- prep: Bcat = [hi(W) | lo(W)] per output row n ----------------
__global__ void prep_w_kernel(const float* __restrict__ Wl,
                              const float* __restrict__ Wr,
                              __nv_bfloat16* __restrict__ Bcat) {
    int idx = blockIdx.x * blockDim.x + threadIdx.x;   // 256*512
    if (idx >= D * 512) return;
    int n = idx >> 9;
    int k = idx & 511;
    float w = (k < D) ? Wl[n * D + k] : Wr[n * D + (k - D)];
    __nv_bfloat16 hi, lo;
    split_bf16(w, hi, lo);
    Bcat[(size_t)n * KA + k] = hi;
    Bcat[(size_t)n * KA + 512 + k] = lo;
}

// ---------------- leaf reduce -> Acat [hi|lo] ----------------
__global__ void leaf_reduce_kernel(const float* __restrict__ h,
                                   __nv_bfloat16* __restrict__ Acat,
                                   int n_par) {
    int idx = blockIdx.x * blockDim.x + threadIdx.x;
    if (idx >= n_par * 512) return;
    int p = idx >> 9;
    int k = idx & 511;
    const float* hp = h + (size_t)p * 1024;
    float u;
    if (k < D) {
        u = hp[k] + (2.0f / 3.0f) * hp[D + k] + (1.0f / 3.0f) * hp[2 * D + k];
    } else {
        int j = k - D;
        u = (1.0f / 3.0f) * hp[D + j] + (2.0f / 3.0f) * hp[2 * D + j] + hp[3 * D + j];
    }
    __nv_bfloat16 hi, lo;
    split_bf16(u, hi, lo);
    Acat[(size_t)p * KA + k] = hi;
    Acat[(size_t)p * KA + 512 + k] = lo;
}

// ---------------- GEMM 128x128 tile + tanh + fused combine ----------------
// 8 warps: 4(m) x 2(n), warp tile 32x64. 24 K chunks of 64, 3-stage cp.async.
__global__ void __launch_bounds__(256, 2)
gemm_fused_kernel(const __nv_bfloat16* __restrict__ A,
                  const __nv_bfloat16* __restrict__ B,
                  const float* __restrict__ bias,
                  __nv_bfloat16* __restrict__ Anext,   // null on last level
                  float* __restrict__ outp,            // non-null on last level
                  int M) {
    extern __shared__ __align__(128) char smem[];
    const uint32_t sbase = smem_u32(smem);
    const int tid = threadIdx.x;
    const int wid = tid >> 5;
    const int lid = tid & 31;
    const int bn = blockIdx.x * 128;
    const int bm = blockIdx.y * 128;

    const char* Ab = (const char*)A;
    const char* Bb = (const char*)B + (size_t)bn * ROWBB;

    auto load_stage = [&](int s, int it) {
        int aCh = (it < 16) ? it : it - 16;   // A: hi 0-7, lo 8-15, hi again
        int bCh = (it < 8) ? it : it - 8;     // B: hi,hi,lo
        uint32_t sA = sbase + s * STAGE;
        uint32_t sB = sA + TILE_B;
#pragma unroll
        for (int i = 0; i < 4; i++) {
            int id = i * 256 + tid;
            int r = id >> 3, c = id & 7;
            bool p = (bm + r) < M;
            const char* src = Ab + (size_t)(bm + r) * ROWA + aCh * 128 + c * 16;
            if (!p) src = Ab;
            cp_async16(sA + r * SROW + c * 16, src, p);
        }
#pragma unroll
        for (int i = 0; i < 4; i++) {
            int id = i * 256 + tid;
            int r = id >> 3, c = id & 7;
            const char* src = Bb + (size_t)r * ROWBB + bCh * 128 + c * 16;
            cp_async16(sB + r * SROW + c * 16, src, true);
        }
        CP_COMMIT();
    };

    float acc[2][8][4];
#pragma unroll
    for (int mf = 0; mf < 2; mf++)
#pragma unroll
        for (int nf = 0; nf < 8; nf++)
#pragma unroll
            for (int q = 0; q < 4; q++) acc[mf][nf][q] = 0.0f;

    const int wm = (wid & 3) * 32;
    const int wn = (wid >> 2) * 64;
    const uint32_t aOff = (uint32_t)(wm + (lid & 7) + ((lid & 8) ? 8 : 0)) * SROW +
                          ((lid & 16) ? 16 : 0);
    const uint32_t bOff = (uint32_t)(wn + (lid & 7) + ((lid & 16) ? 8 : 0)) * SROW +
                          ((lid & 8) ? 16 : 0);

    load_stage(0, 0);
    load_stage(1, 1);
    load_stage(2, 2);

    int s = 0;
    for (int it = 0; it < NIT; it++) {
        if (it + 3 < NIT) {
            asm volatile("cp.async.wait_group 2;" ::: "memory");
        } else {
            asm volatile("cp.async.wait_group 0;" ::: "memory");
        }
        __syncthreads();

        uint32_t sA = sbase + s * STAGE;
        uint32_t aAddr = sA + aOff;
        uint32_t bAddr = sA + TILE_B + bOff;

#pragma unroll
        for (int kk = 0; kk < 4; kk++) {
            uint32_t a0[4], a1[4], bf[4][4];
            ldm_x4(a0, aAddr + kk * 32);
            ldm_x4(a1, aAddr + 16 * SROW + kk * 32);
#pragma unroll
            for (int nf2 = 0; nf2 < 4; nf2++)
                ldm_x4(bf[nf2], bAddr + nf2 * 16 * SROW + kk * 32);
#pragma unroll
            for (int nf2 = 0; nf2 < 4; nf2++) {
                mma_bf16(acc[0][nf2 * 2 + 0], a0, bf[nf2][0], bf[nf2][1]);
                mma_bf16(acc[0][nf2 * 2 + 1], a0, bf[nf2][2], bf[nf2][3]);
                mma_bf16(acc[1][nf2 * 2 + 0], a1, bf[nf2][0], bf[nf2][1]);
                mma_bf16(acc[1][nf2 * 2 + 1], a1, bf[nf2][2], bf[nf2][3]);
            }
        }
        __syncthreads();
        if (it + 3 < NIT) load_stage(s, it + 3);
        s = (s == NSTAGE - 1) ? 0 : s + 1;
    }

    // ---- epilogue: tanh(acc + bias) -> smem h tile (128 x 128, stride HST) ----
    float* hs = (float*)smem;
#pragma unroll
    for (int mf = 0; mf < 2; mf++) {
#pragma unroll
        for (int half = 0; half < 2; half++) {
            int r = wm + mf * 16 + (lid >> 2) + half * 8;
            int grow = bm + r;
            if (grow >= M) continue;
            const float* brow = bias + (size_t)grow * D + bn + wn;
            float* hrow = hs + r * HST + wn;
#pragma unroll
            for (int nf = 0; nf < 8; nf++) {
                int col = nf * 8 + 2 * (lid & 3);
                float2 bv = *(const float2*)(brow + col);
                float x = tanhf(acc[mf][nf][half * 2 + 0] + bv.x);
                float y = tanhf(acc[mf][nf][half * 2 + 1] + bv.y);
                hrow[col] = x;
                hrow[col + 1] = y;
                if (outp) {
                    float* orow = outp + (size_t)grow * D + bn + wn;
                    orow[col] = x;
                    orow[col + 1] = y;
                }
            }
        }
    }
    __syncthreads();

    // ---- fused child-combine: 32 parents x 128 local cols -> Anext ----
    if (Anext) {
        int nPar = M >> 2;
        int p = tid >> 3;          // 0..31
        int g = tid & 7;           // 0..7 -> cols g*16..g*16+15
        int pg = (bm >> 2) + p;
        if (pg < nPar) {
            const float* h0 = hs + (4 * p + 0) * HST;
            const float* h1 = hs + (4 * p + 1) * HST;
            const float* h2 = hs + (4 * p + 2) * HST;
            const float* h3 = hs + (4 * p + 3) * HST;
            __nv_bfloat16* arow = Anext + (size_t)pg * KA;
#pragma unroll
            for (int i = 0; i < 2; i++) {
                int c0 = g * 16 + i * 8;
                __nv_bfloat16 lh[8], ll[8], rh[8], rl[8];
#pragma unroll
                for (int j = 0; j < 8; j++) {
                    float a = h0[c0 + j], b = h1[c0 + j], c = h2[c0 + j], d = h3[c0 + j];
                    float lv = a + (2.0f / 3.0f) * b + (1.0f / 3.0f) * c;
                    float rv = (1.0f / 3.0f) * b + (2.0f / 3.0f) * c + d;
                    split_bf16(lv, lh[j], ll[j]);
                    split_bf16(rv, rh[j], rl[j]);
                }
                int cL = bn + c0;          // left u col (k < 256)
                *(uint4*)(arow + cL) = *(const uint4*)lh;
                *(uint4*)(arow + 512 + cL) = *(const uint4*)ll;
                *(uint4*)(arow + 256 + cL) = *(const uint4*)rh;
                *(uint4*)(arow + 768 + cL) = *(const uint4*)rl;
            }
        }
    }
}

// ---------------- launcher ----------------
extern "C" void kernel_launch(void* const* d_in, const int* in_sizes, int n_in,
                              void* d_out, int out_size) {
    const float* vectors = (const float*)d_in[0];
    const float* Wl = (const float*)d_in[1];
    const float* Wr = (const float*)d_in[2];
    float* out = (float*)d_out;

    __nv_bfloat16 *Acat0, *Acat1, *Bcat;
    cudaGetSymbolAddress((void**)&Acat0, g_Acat0);
    cudaGetSymbolAddress((void**)&Acat1, g_Acat1);
    cudaGetSymbolAddress((void**)&Bcat, g_Bcat);

    cudaFuncSetAttribute(gemm_fused_kernel,
                         cudaFuncAttributeMaxDynamicSharedMemorySize, SMEM_TOTAL);

    prep_w_kernel<<<(D * 512 + 255) / 256, 256>>>(Wl, Wr, Bcat);

    static const int offs[9] = {0, 1, 5, 21, 85, 341, 1365, 5461, 21845};

    const float* leaves = vectors + (size_t)offs[8] * D;
    leaf_reduce_kernel<<<(16384 * 512 + 255) / 256, 256>>>(leaves, Acat0, 16384);

    __nv_bfloat16* Ain = Acat0;
    for (int l = 7; l >= 0; --l) {
        int M = 1 << (2 * l);
        __nv_bfloat16* Anext =
            (l > 0) ? ((Ain == Acat0) ? Acat1 : Acat0) : (__nv_bfloat16*)nullptr;
        float* outp = (l == 0) ? out : nullptr;
        const float* bias = vectors + (size_t)offs[l] * D;

        dim3 grid(2, (M + 127) / 128);
        gemm_fused_kernel<<<grid, 256, SMEM_TOTAL>>>(Ain, Bcat, bias, Anext, outp, M);

        Ain = Anext;
    }
}

// round 6
// speedup vs baseline: 2.3457x; 1.5146x over previous
#include <cuda_runtime.h>
#include <cuda_bf16.h>
#include <cstdint>
#include <math.h>

// CBTree B=4, L=9, d=256.
// Levels 7..4: split-bf16 tensor-core GEMM (A=[hi|lo] K=1024, B=[hi|lo]),
//   24 chunk passes (hi*hi, lo*hi, hi*lo), fused tanh + child-combine epilogue.
// Levels 3..0 (M<=64): fp32 SIMT warp-per-output with combine folded in.

#define D 256
#define KA 1024
#define ROWA 2048
#define ROWBB 2048
#define NIT 24
#define SROW 144
#define TILE_B (128 * SROW)
#define STAGE (2 * TILE_B)
#define NSTAGE 3
#define SMEM_TOTAL (NSTAGE * STAGE)   // 110592
#define HST 132

// ---------------- static device scratch ----------------
__device__ __nv_bfloat16 g_Acat0[16384 * 1024];
__device__ __nv_bfloat16 g_Acat1[16384 * 1024];
__device__ __nv_bfloat16 g_Bcat[256 * 1024];
__device__ float g_hsA[256 * 256];
__device__ float g_hsB[256 * 256];

// ---------------- helpers ----------------
__device__ __forceinline__ uint32_t smem_u32(const void* p) {
    uint32_t a;
    asm("{ .reg .u64 t; cvta.to.shared.u64 t, %1; cvt.u32.u64 %0, t; }" : "=r"(a) : "l"(p));
    return a;
}
__device__ __forceinline__ void cp_async16(uint32_t dst, const void* src, bool pred) {
    int sz = pred ? 16 : 0;
    asm volatile("cp.async.cg.shared.global [%0], [%1], 16, %2;"
                 :: "r"(dst), "l"(src), "r"(sz));
}
#define CP_COMMIT() asm volatile("cp.async.commit_group;" ::: "memory")

__device__ __forceinline__ void ldm_x4(uint32_t* r, uint32_t addr) {
    asm volatile("ldmatrix.sync.aligned.m8n8.x4.shared.b16 {%0,%1,%2,%3}, [%4];"
                 : "=r"(r[0]), "=r"(r[1]), "=r"(r[2]), "=r"(r[3]) : "r"(addr));
}
__device__ __forceinline__ void mma_bf16(float* c, const uint32_t* a, uint32_t b0, uint32_t b1) {
    asm volatile("mma.sync.aligned.m16n8k16.row.col.f32.bf16.bf16.f32 "
                 "{%0,%1,%2,%3}, {%4,%5,%6,%7}, {%8,%9}, {%0,%1,%2,%3};"
                 : "+f"(c[0]), "+f"(c[1]), "+f"(c[2]), "+f"(c[3])
                 : "r"(a[0]), "r"(a[1]), "r"(a[2]), "r"(a[3]), "r"(b0), "r"(b1));
}
__device__ __forceinline__ void split_bf16(float v, __nv_bfloat16& hi, __nv_bfloat16& lo) {
    hi = __float2bfloat16_rn(v);
    lo = __float2bfloat16_rn(v - __bfloat162float(hi));
}

// ---------------- prep: Bcat = [hi(W) | lo(W)] ----------------
__global__ void prep_w_kernel(const float* __restrict__ Wl,
                              const float* __restrict__ Wr,
                              __nv_bfloat16* __restrict__ Bcat) {
    int idx = blockIdx.x * blockDim.x + threadIdx.x;
    if (idx >= D * 512) return;
    int n = idx >> 9;
    int k = idx & 511;
    float w = (k < D) ? Wl[n * D + k] : Wr[n * D + (k - D)];
    __nv_bfloat16 hi, lo;
    split_bf16(w, hi, lo);
    Bcat[(size_t)n * KA + k] = hi;
    Bcat[(size_t)n * KA + 512 + k] = lo;
}

// ---------------- leaf reduce (vectorized) -> Acat [hi|lo] ----------------
__global__ void leaf_reduce_kernel(const float* __restrict__ h,
                                   __nv_bfloat16* __restrict__ Acat,
                                   int n_par) {
    int idx = blockIdx.x * blockDim.x + threadIdx.x;   // n_par * 128 (float4 units of u)
    if (idx >= n_par * 128) return;
    int p = idx >> 7;
    int q = idx & 127;                                 // k = q*4
    const float4* hp = (const float4*)(h + (size_t)p * 1024);
    float4 v;
    if (q < 64) {
        float4 a = hp[q], b = hp[64 + q], c = hp[128 + q];
        v.x = a.x + (2.f/3.f) * b.x + (1.f/3.f) * c.x;
        v.y = a.y + (2.f/3.f) * b.y + (1.f/3.f) * c.y;
        v.z = a.z + (2.f/3.f) * b.z + (1.f/3.f) * c.z;
        v.w = a.w + (2.f/3.f) * b.w + (1.f/3.f) * c.w;
    } else {
        int q2 = q - 64;
        float4 b = hp[64 + q2], c = hp[128 + q2], d = hp[192 + q2];
        v.x = (1.f/3.f) * b.x + (2.f/3.f) * c.x + d.x;
        v.y = (1.f/3.f) * b.y + (2.f/3.f) * c.y + d.y;
        v.z = (1.f/3.f) * b.z + (2.f/3.f) * c.z + d.z;
        v.w = (1.f/3.f) * b.w + (2.f/3.f) * c.w + d.w;
    }
    __nv_bfloat16 hi[4], lo[4];
    split_bf16(v.x, hi[0], lo[0]);
    split_bf16(v.y, hi[1], lo[1]);
    split_bf16(v.z, hi[2], lo[2]);
    split_bf16(v.w, hi[3], lo[3]);
    __nv_bfloat16* arow = Acat + (size_t)p * KA + q * 4;
    *(uint2*)arow = *(const uint2*)hi;
    *(uint2*)(arow + 512) = *(const uint2*)lo;
}

// ---------------- GEMM 128x128 + tanh + fused combine (levels 7..4) ----------------
__global__ void __launch_bounds__(256, 2)
gemm_fused_kernel(const __nv_bfloat16* __restrict__ A,
                  const __nv_bfloat16* __restrict__ B,
                  const float* __restrict__ bias,
                  __nv_bfloat16* __restrict__ Anext,   // null at l=4
                  float* __restrict__ outp,            // fp32 h out at l=4
                  int M) {
    extern __shared__ __align__(128) char smem[];
    const uint32_t sbase = smem_u32(smem);
    const int tid = threadIdx.x;
    const int wid = tid >> 5;
    const int lid = tid & 31;
    const int bn = blockIdx.x * 128;
    const int bm = blockIdx.y * 128;

    const char* Ab = (const char*)A;
    const char* Bb = (const char*)B + (size_t)bn * ROWBB;

    auto load_stage = [&](int s, int it) {
        int aCh = (it < 16) ? it : it - 16;
        int bCh = (it < 8) ? it : it - 8;
        uint32_t sA = sbase + s * STAGE;
        uint32_t sB = sA + TILE_B;
#pragma unroll
        for (int i = 0; i < 4; i++) {
            int id = i * 256 + tid;
            int r = id >> 3, c = id & 7;
            bool p = (bm + r) < M;
            const char* src = Ab + (size_t)(bm + r) * ROWA + aCh * 128 + c * 16;
            if (!p) src = Ab;
            cp_async16(sA + r * SROW + c * 16, src, p);
        }
#pragma unroll
        for (int i = 0; i < 4; i++) {
            int id = i * 256 + tid;
            int r = id >> 3, c = id & 7;
            const char* src = Bb + (size_t)r * ROWBB + bCh * 128 + c * 16;
            cp_async16(sB + r * SROW + c * 16, src, true);
        }
        CP_COMMIT();
    };

    float acc[2][8][4];
#pragma unroll
    for (int mf = 0; mf < 2; mf++)
#pragma unroll
        for (int nf = 0; nf < 8; nf++)
#pragma unroll
            for (int q = 0; q < 4; q++) acc[mf][nf][q] = 0.0f;

    const int wm = (wid & 3) * 32;
    const int wn = (wid >> 2) * 64;
    const uint32_t aOff = (uint32_t)(wm + (lid & 7) + ((lid & 8) ? 8 : 0)) * SROW +
                          ((lid & 16) ? 16 : 0);
    const uint32_t bOff = (uint32_t)(wn + (lid & 7) + ((lid & 16) ? 8 : 0)) * SROW +
                          ((lid & 8) ? 16 : 0);

    load_stage(0, 0);
    load_stage(1, 1);
    load_stage(2, 2);

    int s = 0;
    for (int it = 0; it < NIT; it++) {
        if (it + 3 < NIT) {
            asm volatile("cp.async.wait_group 2;" ::: "memory");
        } else {
            asm volatile("cp.async.wait_group 0;" ::: "memory");
        }
        __syncthreads();

        uint32_t sA = sbase + s * STAGE;
        uint32_t aAddr = sA + aOff;
        uint32_t bAddr = sA + TILE_B + bOff;

#pragma unroll
        for (int kk = 0; kk < 4; kk++) {
            uint32_t a0[4], a1[4], bf[4][4];
            ldm_x4(a0, aAddr + kk * 32);
            ldm_x4(a1, aAddr + 16 * SROW + kk * 32);
#pragma unroll
            for (int nf2 = 0; nf2 < 4; nf2++)
                ldm_x4(bf[nf2], bAddr + nf2 * 16 * SROW + kk * 32);
#pragma unroll
            for (int nf2 = 0; nf2 < 4; nf2++) {
                mma_bf16(acc[0][nf2 * 2 + 0], a0, bf[nf2][0], bf[nf2][1]);
                mma_bf16(acc[0][nf2 * 2 + 1], a0, bf[nf2][2], bf[nf2][3]);
                mma_bf16(acc[1][nf2 * 2 + 0], a1, bf[nf2][0], bf[nf2][1]);
                mma_bf16(acc[1][nf2 * 2 + 1], a1, bf[nf2][2], bf[nf2][3]);
            }
        }
        __syncthreads();
        if (it + 3 < NIT) load_stage(s, it + 3);
        s = (s == NSTAGE - 1) ? 0 : s + 1;
    }

    // ---- epilogue: tanh(acc + bias) -> smem h tile ----
    float* hs = (float*)smem;
#pragma unroll
    for (int mf = 0; mf < 2; mf++) {
#pragma unroll
        for (int half = 0; half < 2; half++) {
            int r = wm + mf * 16 + (lid >> 2) + half * 8;
            int grow = bm + r;
            if (grow >= M) continue;
            const float* brow = bias + (size_t)grow * D + bn + wn;
            float* hrow = hs + r * HST + wn;
#pragma unroll
            for (int nf = 0; nf < 8; nf++) {
                int col = nf * 8 + 2 * (lid & 3);
                float2 bv = *(const float2*)(brow + col);
                float x = tanhf(acc[mf][nf][half * 2 + 0] + bv.x);
                float y = tanhf(acc[mf][nf][half * 2 + 1] + bv.y);
                hrow[col] = x;
                hrow[col + 1] = y;
                if (outp) {
                    float* orow = outp + (size_t)grow * D + bn + wn;
                    orow[col] = x;
                    orow[col + 1] = y;
                }
            }
        }
    }
    __syncthreads();

    // ---- fused child-combine -> Anext ----
    if (Anext) {
        int nPar = M >> 2;
        int p = tid >> 3;
        int g = tid & 7;
        int pg = (bm >> 2) + p;
        if (pg < nPar) {
            const float* h0 = hs + (4 * p + 0) * HST;
            const float* h1 = hs + (4 * p + 1) * HST;
            const float* h2 = hs + (4 * p + 2) * HST;
            const float* h3 = hs + (4 * p + 3) * HST;
            __nv_bfloat16* arow = Anext + (size_t)pg * KA;
#pragma unroll
            for (int i = 0; i < 2; i++) {
                int c0 = g * 16 + i * 8;
                __nv_bfloat16 lh[8], ll[8], rh[8], rl[8];
#pragma unroll
                for (int j = 0; j < 8; j++) {
                    float a = h0[c0 + j], b = h1[c0 + j], c = h2[c0 + j], d = h3[c0 + j];
                    float lv = a + (2.f/3.f) * b + (1.f/3.f) * c;
                    float rv = (1.f/3.f) * b + (2.f/3.f) * c + d;
                    split_bf16(lv, lh[j], ll[j]);
                    split_bf16(rv, rh[j], rl[j]);
                }
                int cL = bn + c0;
                *(uint4*)(arow + cL) = *(const uint4*)lh;
                *(uint4*)(arow + 512 + cL) = *(const uint4*)ll;
                *(uint4*)(arow + 256 + cL) = *(const uint4*)rh;
                *(uint4*)(arow + 768 + cL) = *(const uint4*)rl;
            }
        }
    }
}

// ---------------- small levels (M<=64): fp32 warp-per-output ----------------
__global__ void __launch_bounds__(256)
small_level_kernel(const float* __restrict__ hprev,
                   const float* __restrict__ Wl,
                   const float* __restrict__ Wr,
                   const float* __restrict__ bias,
                   float* __restrict__ hout, int Mout) {
    int gw = (blockIdx.x * blockDim.x + threadIdx.x) >> 5;
    int lid = threadIdx.x & 31;
    if (gw >= Mout * D) return;
    int p = gw >> 8;
    int n = gw & 255;
    const float* h0 = hprev + (size_t)(4 * p) * D;
    const float* wl = Wl + (size_t)n * D;
    const float* wr = Wr + (size_t)n * D;
    float acc = 0.f;
#pragma unroll
    for (int i = 0; i < 8; i++) {
        int k = lid + i * 32;
        float a = h0[k], b = h0[D + k], c = h0[2 * D + k], d = h0[3 * D + k];
        float uL = a + (2.f/3.f) * b + (1.f/3.f) * c;
        float uR = (1.f/3.f) * b + (2.f/3.f) * c + d;
        acc = fmaf(uL, wl[k], acc);
        acc = fmaf(uR, wr[k], acc);
    }
#pragma unroll
    for (int o = 16; o; o >>= 1) acc += __shfl_xor_sync(0xffffffffu, acc, o);
    if (lid == 0)
        hout[(size_t)p * D + n] = tanhf(acc + bias[(size_t)p * D + n]);
}

// ---------------- launcher ----------------
extern "C" void kernel_launch(void* const* d_in, const int* in_sizes, int n_in,
                              void* d_out, int out_size) {
    const float* vectors = (const float*)d_in[0];
    const float* Wl = (const float*)d_in[1];
    const float* Wr = (const float*)d_in[2];
    float* out = (float*)d_out;

    __nv_bfloat16 *Acat0, *Acat1, *Bcat;
    float *hsA, *hsB;
    cudaGetSymbolAddress((void**)&Acat0, g_Acat0);
    cudaGetSymbolAddress((void**)&Acat1, g_Acat1);
    cudaGetSymbolAddress((void**)&Bcat, g_Bcat);
    cudaGetSymbolAddress((void**)&hsA, g_hsA);
    cudaGetSymbolAddress((void**)&hsB, g_hsB);

    cudaFuncSetAttribute(gemm_fused_kernel,
                         cudaFuncAttributeMaxDynamicSharedMemorySize, SMEM_TOTAL);
    cudaFuncSetAttribute(gemm_fused_kernel,
                         cudaFuncAttributePreferredSharedMemoryCarveout, 100);

    prep_w_kernel<<<(D * 512 + 255) / 256, 256>>>(Wl, Wr, Bcat);

    static const int offs[9] = {0, 1, 5, 21, 85, 341, 1365, 5461, 21845};

    const float* leaves = vectors + (size_t)offs[8] * D;
    leaf_reduce_kernel<<<(16384 * 128 + 255) / 256, 256>>>(leaves, Acat0, 16384);

    // Tensor-core levels 7..4
    __nv_bfloat16* Ain = Acat0;
    for (int l = 7; l >= 4; --l) {
        int M = 1 << (2 * l);
        __nv_bfloat16* Anext =
            (l > 4) ? ((Ain == Acat0) ? Acat1 : Acat0) : (__nv_bfloat16*)nullptr;
        float* outp = (l == 4) ? hsA : nullptr;
        const float* bias = vectors + (size_t)offs[l] * D;

        dim3 grid(2, (M + 127) / 128);
        gemm_fused_kernel<<<grid, 256, SMEM_TOTAL>>>(Ain, Bcat, bias, Anext, outp, M);
        Ain = Anext;
    }

    // SIMT fp32 levels 3..0
    const float* hin = hsA;
    for (int l = 3; l >= 0; --l) {
        int M = 1 << (2 * l);
        float* hout = (l == 0) ? out : ((l & 1) ? hsB : hsA);
        if (l == 2) hout = hsB;   // alternate: l=3->hsB, l=2->hsA would clash; use explicit
        // explicit ping-pong: hin starts hsA (l=4 output)
        // l=3: hsA -> hsB ; l=2: hsB -> hsA ; l=1: hsA -> hsB ; l=0: hsB -> out
        hout = (l == 0) ? out : ((l & 1) ? hsB : hsA);
        const float* bias = vectors + (size_t)offs[l] * D;
        int nwarps = M * D;
        small_level_kernel<<<(nwarps * 32 + 255) / 256, 256>>>(hin, Wl, Wr, bias, hout, M);
        hin = hout;
    }
}

// round 7
// speedup vs baseline: 3.1143x; 1.3277x over previous
#include <cuda_runtime.h>
#include <cuda_bf16.h>
#include <cstdint>
#include <math.h>

// CBTree B=4, L=9, d=256.
// Levels 7..4: split-bf16 tensor-core GEMM (A=[hi|lo] K=1024, B=[hi|lo]),
//   24 logical chunk passes (hi*hi, lo*hi, hi*lo), SPLIT-K across CTAs into
//   fp32 partials; epilogue kernel: sum + bias + tanh + child-combine -> Anext.
// Levels 3..0: fp32 SIMT warp-per-output.

#define D 256
#define KA 1024
#define ROWA 2048
#define ROWBB 2048
#define NCHUNK 24
#define SROW 144
#define TILE_B (128 * SROW)
#define STAGE (2 * TILE_B)          // 36864
#define NSTAGE 2
#define SMEM_TOTAL (NSTAGE * STAGE) // 73728
#define HST 132

// ---------------- static device scratch ----------------
__device__ __nv_bfloat16 g_Acat0[16384 * 1024];
__device__ __nv_bfloat16 g_Acat1[16384 * 1024];
__device__ __nv_bfloat16 g_Bcat[256 * 1024];
__device__ float g_part[16384 * 256];     // 16 MB split-K partials (max over levels)
__device__ float g_hsA[256 * 256];
__device__ float g_hsB[256 * 256];

// ---------------- helpers ----------------
__device__ __forceinline__ uint32_t smem_u32(const void* p) {
    uint32_t a;
    asm("{ .reg .u64 t; cvta.to.shared.u64 t, %1; cvt.u32.u64 %0, t; }" : "=r"(a) : "l"(p));
    return a;
}
__device__ __forceinline__ void cp_async16(uint32_t dst, const void* src) {
    asm volatile("cp.async.cg.shared.global [%0], [%1], 16;"
                 :: "r"(dst), "l"(src));
}
#define CP_COMMIT() asm volatile("cp.async.commit_group;" ::: "memory")

__device__ __forceinline__ void ldm_x4(uint32_t* r, uint32_t addr) {
    asm volatile("ldmatrix.sync.aligned.m8n8.x4.shared.b16 {%0,%1,%2,%3}, [%4];"
                 : "=r"(r[0]), "=r"(r[1]), "=r"(r[2]), "=r"(r[3]) : "r"(addr));
}
__device__ __forceinline__ void mma_bf16(float* c, const uint32_t* a, uint32_t b0, uint32_t b1) {
    asm volatile("mma.sync.aligned.m16n8k16.row.col.f32.bf16.bf16.f32 "
                 "{%0,%1,%2,%3}, {%4,%5,%6,%7}, {%8,%9}, {%0,%1,%2,%3};"
                 : "+f"(c[0]), "+f"(c[1]), "+f"(c[2]), "+f"(c[3])
                 : "r"(a[0]), "r"(a[1]), "r"(a[2]), "r"(a[3]), "r"(b0), "r"(b1));
}
__device__ __forceinline__ void split_bf16(float v, __nv_bfloat16& hi, __nv_bfloat16& lo) {
    hi = __float2bfloat16_rn(v);
    lo = __float2bfloat16_rn(v - __bfloat162float(hi));
}

// ---------------- prep: Bcat = [hi(W) | lo(W)] ----------------
__global__ void prep_w_kernel(const float* __restrict__ Wl,
                              const float* __restrict__ Wr,
                              __nv_bfloat16* __restrict__ Bcat) {
    int idx = blockIdx.x * blockDim.x + threadIdx.x;
    if (idx >= D * 512) return;
    int n = idx >> 9;
    int k = idx & 511;
    float w = (k < D) ? Wl[n * D + k] : Wr[n * D + (k - D)];
    __nv_bfloat16 hi, lo;
    split_bf16(w, hi, lo);
    Bcat[(size_t)n * KA + k] = hi;
    Bcat[(size_t)n * KA + 512 + k] = lo;
}

// ---------------- leaf reduce (vectorized) -> Acat [hi|lo] ----------------
__global__ void leaf_reduce_kernel(const float* __restrict__ h,
                                   __nv_bfloat16* __restrict__ Acat,
                                   int n_par) {
    int idx = blockIdx.x * blockDim.x + threadIdx.x;   // n_par * 128 float4 units
    if (idx >= n_par * 128) return;
    int p = idx >> 7;
    int q = idx & 127;
    const float4* hp = (const float4*)(h + (size_t)p * 1024);
    float4 v;
    if (q < 64) {
        float4 a = hp[q], b = hp[64 + q], c = hp[128 + q];
        v.x = a.x + (2.f/3.f) * b.x + (1.f/3.f) * c.x;
        v.y = a.y + (2.f/3.f) * b.y + (1.f/3.f) * c.y;
        v.z = a.z + (2.f/3.f) * b.z + (1.f/3.f) * c.z;
        v.w = a.w + (2.f/3.f) * b.w + (1.f/3.f) * c.w;
    } else {
        int q2 = q - 64;
        float4 b = hp[64 + q2], c = hp[128 + q2], d = hp[192 + q2];
        v.x = (1.f/3.f) * b.x + (2.f/3.f) * c.x + d.x;
        v.y = (1.f/3.f) * b.y + (2.f/3.f) * c.y + d.y;
        v.z = (1.f/3.f) * b.z + (2.f/3.f) * c.z + d.z;
        v.w = (1.f/3.f) * b.w + (2.f/3.f) * c.w + d.w;
    }
    __nv_bfloat16 hi[4], lo[4];
    split_bf16(v.x, hi[0], lo[0]);
    split_bf16(v.y, hi[1], lo[1]);
    split_bf16(v.z, hi[2], lo[2]);
    split_bf16(v.w, hi[3], lo[3]);
    __nv_bfloat16* arow = Acat + (size_t)p * KA + q * 4;
    *(uint2*)arow = *(const uint2*)hi;
    *(uint2*)(arow + 512) = *(const uint2*)lo;
}

// ---------------- split-K partial GEMM (128x128 tile) ----------------
// blockIdx = (n_tile[2], m_tile, split). Each CTA runs chunks [z*cnt, (z+1)*cnt),
// writes fp32 partial tile to P + z*M*256. M is a multiple of 128.
__global__ void __launch_bounds__(256, 2)
gemm_partial_kernel(const __nv_bfloat16* __restrict__ A,
                    const __nv_bfloat16* __restrict__ B,
                    float* __restrict__ P,
                    int M, int cnt) {
    extern __shared__ __align__(128) char smem[];
    const uint32_t sbase = smem_u32(smem);
    const int tid = threadIdx.x;
    const int wid = tid >> 5;
    const int lid = tid & 31;
    const int bn = blockIdx.x * 128;
    const int bm = blockIdx.y * 128;
    const int c0 = blockIdx.z * cnt;

    const char* Ab = (const char*)A + (size_t)bm * ROWA;
    const char* Bb = (const char*)B + (size_t)bn * ROWBB;
    float* Pb = P + ((size_t)blockIdx.z * M + bm) * D + bn;

    auto load_stage = [&](int s, int it) {
        int aCh = (it < 16) ? it : it - 16;
        int bCh = (it < 8) ? it : it - 8;
        uint32_t sA = sbase + s * STAGE;
        uint32_t sB = sA + TILE_B;
#pragma unroll
        for (int i = 0; i < 4; i++) {
            int id = i * 256 + tid;
            int r = id >> 3, c = id & 7;
            cp_async16(sA + r * SROW + c * 16,
                       Ab + (size_t)r * ROWA + aCh * 128 + c * 16);
        }
#pragma unroll
        for (int i = 0; i < 4; i++) {
            int id = i * 256 + tid;
            int r = id >> 3, c = id & 7;
            cp_async16(sB + r * SROW + c * 16,
                       Bb + (size_t)r * ROWBB + bCh * 128 + c * 16);
        }
        CP_COMMIT();
    };

    float acc[2][8][4];
#pragma unroll
    for (int mf = 0; mf < 2; mf++)
#pragma unroll
        for (int nf = 0; nf < 8; nf++)
#pragma unroll
            for (int q = 0; q < 4; q++) acc[mf][nf][q] = 0.0f;

    const int wm = (wid & 3) * 32;
    const int wn = (wid >> 2) * 64;
    const uint32_t aOff = (uint32_t)(wm + (lid & 7) + ((lid & 8) ? 8 : 0)) * SROW +
                          ((lid & 16) ? 16 : 0);
    const uint32_t bOff = (uint32_t)(wn + (lid & 7) + ((lid & 16) ? 8 : 0)) * SROW +
                          ((lid & 8) ? 16 : 0);

    load_stage(0, c0);
    if (cnt > 1) load_stage(1, c0 + 1);

    for (int i = 0; i < cnt; i++) {
        if (i + 1 < cnt) {
            asm volatile("cp.async.wait_group 1;" ::: "memory");
        } else {
            asm volatile("cp.async.wait_group 0;" ::: "memory");
        }
        __syncthreads();

        uint32_t sA = sbase + (i & 1) * STAGE;
        uint32_t aAddr = sA + aOff;
        uint32_t bAddr = sA + TILE_B + bOff;

#pragma unroll
        for (int kk = 0; kk < 4; kk++) {
            uint32_t a0[4], a1[4], bf[4][4];
            ldm_x4(a0, aAddr + kk * 32);
            ldm_x4(a1, aAddr + 16 * SROW + kk * 32);
#pragma unroll
            for (int nf2 = 0; nf2 < 4; nf2++)
                ldm_x4(bf[nf2], bAddr + nf2 * 16 * SROW + kk * 32);
#pragma unroll
            for (int nf2 = 0; nf2 < 4; nf2++) {
                mma_bf16(acc[0][nf2 * 2 + 0], a0, bf[nf2][0], bf[nf2][1]);
                mma_bf16(acc[0][nf2 * 2 + 1], a0, bf[nf2][2], bf[nf2][3]);
                mma_bf16(acc[1][nf2 * 2 + 0], a1, bf[nf2][0], bf[nf2][1]);
                mma_bf16(acc[1][nf2 * 2 + 1], a1, bf[nf2][2], bf[nf2][3]);
            }
        }
        __syncthreads();
        if (i + 2 < cnt) load_stage(i & 1, c0 + i + 2);
    }

    // ---- write fp32 partial tile ----
#pragma unroll
    for (int mf = 0; mf < 2; mf++) {
#pragma unroll
        for (int half = 0; half < 2; half++) {
            int r = wm + mf * 16 + (lid >> 2) + half * 8;
            float* prow = Pb + (size_t)r * D + wn;
#pragma unroll
            for (int nf = 0; nf < 8; nf++) {
                int col = nf * 8 + 2 * (lid & 3);
                float2 o;
                o.x = acc[mf][nf][half * 2 + 0];
                o.y = acc[mf][nf][half * 2 + 1];
                *(float2*)(prow + col) = o;
            }
        }
    }
}

// ---------------- epilogue: sum splits + bias + tanh + combine + split ----------------
// One thread per (parent, col-quad): (M/4) * 64 threads.
__global__ void __launch_bounds__(256)
epilogue_combine_kernel(const float* __restrict__ P, int S,
                        const float* __restrict__ bias,
                        __nv_bfloat16* __restrict__ Anext,   // may be null
                        float* __restrict__ hout,            // may be null
                        int M) {
    int idx = blockIdx.x * blockDim.x + threadIdx.x;
    int nPar = M >> 2;
    if (idx >= nPar * 64) return;
    int p = idx >> 6;
    int q = idx & 63;

    float4 h[4];
#pragma unroll
    for (int j = 0; j < 4; j++) {
        int row = 4 * p + j;
        float4 sum = *(const float4*)(P + (size_t)row * D + q * 4);
        for (int s = 1; s < S; s++) {
            float4 t = *(const float4*)(P + ((size_t)s * M + row) * D + q * 4);
            sum.x += t.x; sum.y += t.y; sum.z += t.z; sum.w += t.w;
        }
        float4 bv = *(const float4*)(bias + (size_t)row * D + q * 4);
        h[j].x = tanhf(sum.x + bv.x);
        h[j].y = tanhf(sum.y + bv.y);
        h[j].z = tanhf(sum.z + bv.z);
        h[j].w = tanhf(sum.w + bv.w);
        if (hout) *(float4*)(hout + (size_t)row * D + q * 4) = h[j];
    }

    if (Anext) {
        float4 uL, uR;
        uL.x = h[0].x + (2.f/3.f) * h[1].x + (1.f/3.f) * h[2].x;
        uL.y = h[0].y + (2.f/3.f) * h[1].y + (1.f/3.f) * h[2].y;
        uL.z = h[0].z + (2.f/3.f) * h[1].z + (1.f/3.f) * h[2].z;
        uL.w = h[0].w + (2.f/3.f) * h[1].w + (1.f/3.f) * h[2].w;
        uR.x = (1.f/3.f) * h[1].x + (2.f/3.f) * h[2].x + h[3].x;
        uR.y = (1.f/3.f) * h[1].y + (2.f/3.f) * h[2].y + h[3].y;
        uR.z = (1.f/3.f) * h[1].z + (2.f/3.f) * h[2].z + h[3].z;
        uR.w = (1.f/3.f) * h[1].w + (2.f/3.f) * h[2].w + h[3].w;

        __nv_bfloat16 lh[4], ll[4], rh[4], rl[4];
        split_bf16(uL.x, lh[0], ll[0]);
        split_bf16(uL.y, lh[1], ll[1]);
        split_bf16(uL.z, lh[2], ll[2]);
        split_bf16(uL.w, lh[3], ll[3]);
        split_bf16(uR.x, rh[0], rl[0]);
        split_bf16(uR.y, rh[1], rl[1]);
        split_bf16(uR.z, rh[2], rl[2]);
        split_bf16(uR.w, rh[3], rl[3]);

        __nv_bfloat16* arow = Anext + (size_t)p * KA + q * 4;
        *(uint2*)(arow)       = *(const uint2*)lh;   // hi L
        *(uint2*)(arow + 256) = *(const uint2*)rh;   // hi R
        *(uint2*)(arow + 512) = *(const uint2*)ll;   // lo L
        *(uint2*)(arow + 768) = *(const uint2*)rl;   // lo R
    }
}

// ---------------- small levels (M<=64): fp32 warp-per-output ----------------
__global__ void __launch_bounds__(256)
small_level_kernel(const float* __restrict__ hprev,
                   const float* __restrict__ Wl,
                   const float* __restrict__ Wr,
                   const float* __restrict__ bias,
                   float* __restrict__ hout, int Mout) {
    int gw = (blockIdx.x * blockDim.x + threadIdx.x) >> 5;
    int lid = threadIdx.x & 31;
    if (gw >= Mout * D) return;
    int p = gw >> 8;
    int n = gw & 255;
    const float* h0 = hprev + (size_t)(4 * p) * D;
    const float* wl = Wl + (size_t)n * D;
    const float* wr = Wr + (size_t)n * D;
    float acc = 0.f;
#pragma unroll
    for (int i = 0; i < 8; i++) {
        int k = lid + i * 32;
        float a = h0[k], b = h0[D + k], c = h0[2 * D + k], d = h0[3 * D + k];
        float uL = a + (2.f/3.f) * b + (1.f/3.f) * c;
        float uR = (1.f/3.f) * b + (2.f/3.f) * c + d;
        acc = fmaf(uL, wl[k], acc);
        acc = fmaf(uR, wr[k], acc);
    }
#pragma unroll
    for (int o = 16; o; o >>= 1) acc += __shfl_xor_sync(0xffffffffu, acc, o);
    if (lid == 0)
        hout[(size_t)p * D + n] = tanhf(acc + bias[(size_t)p * D + n]);
}

// ---------------- launcher ----------------
extern "C" void kernel_launch(void* const* d_in, const int* in_sizes, int n_in,
                              void* d_out, int out_size) {
    const float* vectors = (const float*)d_in[0];
    const float* Wl = (const float*)d_in[1];
    const float* Wr = (const float*)d_in[2];
    float* out = (float*)d_out;

    __nv_bfloat16 *Acat0, *Acat1, *Bcat;
    float *part, *hsA, *hsB;
    cudaGetSymbolAddress((void**)&Acat0, g_Acat0);
    cudaGetSymbolAddress((void**)&Acat1, g_Acat1);
    cudaGetSymbolAddress((void**)&Bcat, g_Bcat);
    cudaGetSymbolAddress((void**)&part, g_part);
    cudaGetSymbolAddress((void**)&hsA, g_hsA);
    cudaGetSymbolAddress((void**)&hsB, g_hsB);

    cudaFuncSetAttribute(gemm_partial_kernel,
                         cudaFuncAttributeMaxDynamicSharedMemorySize, SMEM_TOTAL);
    cudaFuncSetAttribute(gemm_partial_kernel,
                         cudaFuncAttributePreferredSharedMemoryCarveout, 100);

    prep_w_kernel<<<(D * 512 + 255) / 256, 256>>>(Wl, Wr, Bcat);

    static const int offs[9] = {0, 1, 5, 21, 85, 341, 1365, 5461, 21845};

    const float* leaves = vectors + (size_t)offs[8] * D;
    leaf_reduce_kernel<<<(16384 * 128 + 255) / 256, 256>>>(leaves, Acat0, 16384);

    // split-K config per level: S * cnt = 24
    static const int SPLITS[8] = {0, 0, 0, 0, 12, 8, 4, 1};   // index by l
    __nv_bfloat16* Ain = Acat0;
    for (int l = 7; l >= 4; --l) {
        int M = 1 << (2 * l);
        int S = SPLITS[l];
        int cnt = NCHUNK / S;
        __nv_bfloat16* Anext =
            (l > 4) ? ((Ain == Acat0) ? Acat1 : Acat0) : (__nv_bfloat16*)nullptr;
        float* hout = (l == 4) ? hsA : nullptr;
        const float* bias = vectors + (size_t)offs[l] * D;

        dim3 grid(2, M / 128, S);
        gemm_partial_kernel<<<grid, 256, SMEM_TOTAL>>>(Ain, Bcat, part, M, cnt);

        int nthr = (M / 4) * 64;
        epilogue_combine_kernel<<<(nthr + 255) / 256, 256>>>(part, S, bias, Anext, hout, M);

        Ain = Anext;
    }

    // SIMT fp32 levels 3..0: hsA -> hsB -> hsA -> hsB -> out
    const float* hin = hsA;
    for (int l = 3; l >= 0; --l) {
        int M = 1 << (2 * l);
        float* hout = (l == 0) ? out : ((l & 1) ? hsB : hsA);
        const float* bias = vectors + (size_t)offs[l] * D;
        int nwarps = M * D;
        small_level_kernel<<<(nwarps * 32 + 255) / 256, 256>>>(hin, Wl, Wr, bias, hout, M);
        hin = hout;
    }
}

// round 8
// speedup vs baseline: 3.1158x; 1.0005x over previous
#include <cuda_runtime.h>
#include <cuda_bf16.h>
#include <cstdint>
#include <math.h>

// CBTree B=4, L=9, d=256.
// l=7: full-K fused GEMM (tanh+combine epilogue -> Anext). l=6..4: split-K
// partial GEMM + epilogue kernel. l=3..0: fp32 SIMT warp-per-output.
// Split-bf16: A=[hi|lo] (K=1024), B=[hi|lo]; 24 chunk passes hi*hi, lo*hi, hi*lo.

#define D 256
#define KA 1024
#define ROWA 2048
#define ROWBB 2048
#define NCHUNK 24
#define SROW 144
#define TILE_B (128 * SROW)
#define STAGE (2 * TILE_B)            // 36864
#define NSTAGE 3
#define SMEM_TOTAL (NSTAGE * STAGE)   // 110592 (2 CTAs/SM: 221KB <= 228KB)
#define HST 132

// ---------------- static device scratch ----------------
__device__ __nv_bfloat16 g_Acat0[16384 * 1024];
__device__ __nv_bfloat16 g_Acat1[16384 * 1024];
__device__ __nv_bfloat16 g_Bcat[256 * 1024];
__device__ float g_part[16384 * 256];
__device__ float g_hsA[256 * 256];
__device__ float g_hsB[256 * 256];

// ---------------- helpers ----------------
__device__ __forceinline__ uint32_t smem_u32(const void* p) {
    uint32_t a;
    asm("{ .reg .u64 t; cvta.to.shared.u64 t, %1; cvt.u32.u64 %0, t; }" : "=r"(a) : "l"(p));
    return a;
}
__device__ __forceinline__ void cp_async16(uint32_t dst, const void* src) {
    asm volatile("cp.async.cg.shared.global [%0], [%1], 16;" :: "r"(dst), "l"(src));
}
#define CP_COMMIT() asm volatile("cp.async.commit_group;" ::: "memory")

__device__ __forceinline__ void ldm_x4(uint32_t* r, uint32_t addr) {
    asm volatile("ldmatrix.sync.aligned.m8n8.x4.shared.b16 {%0,%1,%2,%3}, [%4];"
                 : "=r"(r[0]), "=r"(r[1]), "=r"(r[2]), "=r"(r[3]) : "r"(addr));
}
__device__ __forceinline__ void mma_bf16(float* c, const uint32_t* a, uint32_t b0, uint32_t b1) {
    asm volatile("mma.sync.aligned.m16n8k16.row.col.f32.bf16.bf16.f32 "
                 "{%0,%1,%2,%3}, {%4,%5,%6,%7}, {%8,%9}, {%0,%1,%2,%3};"
                 : "+f"(c[0]), "+f"(c[1]), "+f"(c[2]), "+f"(c[3])
                 : "r"(a[0]), "r"(a[1]), "r"(a[2]), "r"(a[3]), "r"(b0), "r"(b1));
}
__device__ __forceinline__ void split_bf16(float v, __nv_bfloat16& hi, __nv_bfloat16& lo) {
    hi = __float2bfloat16_rn(v);
    lo = __float2bfloat16_rn(v - __bfloat162float(hi));
}

// Per-chunk compute: fragment double-buffered ldmatrix + 16 MMA per kk.
__device__ __forceinline__ void compute_chunk(uint32_t aAddr, uint32_t bAddr,
                                              float acc[2][8][4]) {
    uint32_t a[2][2][4], b[2][4][4];
    ldm_x4(a[0][0], aAddr);
    ldm_x4(a[0][1], aAddr + 16 * SROW);
#pragma unroll
    for (int nf = 0; nf < 4; nf++) ldm_x4(b[0][nf], bAddr + nf * 16 * SROW);
#pragma unroll
    for (int kk = 0; kk < 4; kk++) {
        int cur = kk & 1, nxt = cur ^ 1;
        if (kk < 3) {
            ldm_x4(a[nxt][0], aAddr + (kk + 1) * 32);
            ldm_x4(a[nxt][1], aAddr + 16 * SROW + (kk + 1) * 32);
#pragma unroll
            for (int nf = 0; nf < 4; nf++)
                ldm_x4(b[nxt][nf], bAddr + nf * 16 * SROW + (kk + 1) * 32);
        }
#pragma unroll
        for (int nf = 0; nf < 4; nf++) {
            mma_bf16(acc[0][nf * 2 + 0], a[cur][0], b[cur][nf][0], b[cur][nf][1]);
            mma_bf16(acc[0][nf * 2 + 1], a[cur][0], b[cur][nf][2], b[cur][nf][3]);
            mma_bf16(acc[1][nf * 2 + 0], a[cur][1], b[cur][nf][0], b[cur][nf][1]);
            mma_bf16(acc[1][nf * 2 + 1], a[cur][1], b[cur][nf][2], b[cur][nf][3]);
        }
    }
}

// ---------------- prep: Bcat = [hi(W) | lo(W)] ----------------
__global__ void prep_w_kernel(const float* __restrict__ Wl,
                              const float* __restrict__ Wr,
                              __nv_bfloat16* __restrict__ Bcat) {
    int idx = blockIdx.x * blockDim.x + threadIdx.x;
    if (idx >= D * 512) return;
    int n = idx >> 9;
    int k = idx & 511;
    float w = (k < D) ? Wl[n * D + k] : Wr[n * D + (k - D)];
    __nv_bfloat16 hi, lo;
    split_bf16(w, hi, lo);
    Bcat[(size_t)n * KA + k] = hi;
    Bcat[(size_t)n * KA + 512 + k] = lo;
}

// ---------------- leaf reduce -> Acat [hi|lo] ----------------
__global__ void leaf_reduce_kernel(const float* __restrict__ h,
                                   __nv_bfloat16* __restrict__ Acat,
                                   int n_par) {
    int idx = blockIdx.x * blockDim.x + threadIdx.x;
    if (idx >= n_par * 128) return;
    int p = idx >> 7;
    int q = idx & 127;
    const float4* hp = (const float4*)(h + (size_t)p * 1024);
    float4 v;
    if (q < 64) {
        float4 a = hp[q], b = hp[64 + q], c = hp[128 + q];
        v.x = a.x + (2.f/3.f) * b.x + (1.f/3.f) * c.x;
        v.y = a.y + (2.f/3.f) * b.y + (1.f/3.f) * c.y;
        v.z = a.z + (2.f/3.f) * b.z + (1.f/3.f) * c.z;
        v.w = a.w + (2.f/3.f) * b.w + (1.f/3.f) * c.w;
    } else {
        int q2 = q - 64;
        float4 b = hp[64 + q2], c = hp[128 + q2], d = hp[192 + q2];
        v.x = (1.f/3.f) * b.x + (2.f/3.f) * c.x + d.x;
        v.y = (1.f/3.f) * b.y + (2.f/3.f) * c.y + d.y;
        v.z = (1.f/3.f) * b.z + (2.f/3.f) * c.z + d.z;
        v.w = (1.f/3.f) * b.w + (2.f/3.f) * c.w + d.w;
    }
    __nv_bfloat16 hi[4], lo[4];
    split_bf16(v.x, hi[0], lo[0]);
    split_bf16(v.y, hi[1], lo[1]);
    split_bf16(v.z, hi[2], lo[2]);
    split_bf16(v.w, hi[3], lo[3]);
    __nv_bfloat16* arow = Acat + (size_t)p * KA + q * 4;
    *(uint2*)arow = *(const uint2*)hi;
    *(uint2*)(arow + 512) = *(const uint2*)lo;
}

// ======== shared loader (macro-ish via inline fn) ========
__device__ __forceinline__ void load_stage_g(uint32_t sbase, int slot, int it,
                                             const char* Ab, const char* Bb, int tid) {
    int aCh = (it < 16) ? it : it - 16;
    int bCh = (it < 8) ? it : it - 8;
    uint32_t sA = sbase + slot * STAGE;
    uint32_t sB = sA + TILE_B;
#pragma unroll
    for (int i = 0; i < 4; i++) {
        int id = i * 256 + tid;
        int r = id >> 3, c = id & 7;
        cp_async16(sA + r * SROW + c * 16, Ab + (size_t)r * ROWA + aCh * 128 + c * 16);
    }
#pragma unroll
    for (int i = 0; i < 4; i++) {
        int id = i * 256 + tid;
        int r = id >> 3, c = id & 7;
        cp_async16(sB + r * SROW + c * 16, Bb + (size_t)r * ROWBB + bCh * 128 + c * 16);
    }
    CP_COMMIT();
}

// ---------------- l=7: full-K GEMM + fused tanh/combine epilogue ----------------
__global__ void __launch_bounds__(256, 2)
gemm_fused_l7(const __nv_bfloat16* __restrict__ A,
              const __nv_bfloat16* __restrict__ B,
              const float* __restrict__ bias,
              __nv_bfloat16* __restrict__ Anext, int M) {
    extern __shared__ __align__(128) char smem[];
    const uint32_t sbase = smem_u32(smem);
    const int tid = threadIdx.x;
    const int wid = tid >> 5;
    const int lid = tid & 31;
    const int bn = blockIdx.x * 128;
    const int bm = blockIdx.y * 128;

    const char* Ab = (const char*)A + (size_t)bm * ROWA;
    const char* Bb = (const char*)B + (size_t)bn * ROWBB;

    float acc[2][8][4];
#pragma unroll
    for (int mf = 0; mf < 2; mf++)
#pragma unroll
        for (int nf = 0; nf < 8; nf++)
#pragma unroll
            for (int q = 0; q < 4; q++) acc[mf][nf][q] = 0.0f;

    const int wm = (wid & 3) * 32;
    const int wn = (wid >> 2) * 64;
    const uint32_t aOff = (uint32_t)(wm + (lid & 7) + ((lid & 8) ? 8 : 0)) * SROW +
                          ((lid & 16) ? 16 : 0);
    const uint32_t bOff = (uint32_t)(wn + (lid & 7) + ((lid & 16) ? 8 : 0)) * SROW +
                          ((lid & 8) ? 16 : 0);

    load_stage_g(sbase, 0, 0, Ab, Bb, tid);
    load_stage_g(sbase, 1, 1, Ab, Bb, tid);

    for (int it = 0; it < NCHUNK; it++) {
        if (it + 2 < NCHUNK) {
            asm volatile("cp.async.wait_group 1;" ::: "memory");
        } else {
            asm volatile("cp.async.wait_group 0;" ::: "memory");
        }
        __syncthreads();
        if (it + 2 < NCHUNK)
            load_stage_g(sbase, (it + 2) % NSTAGE, it + 2, Ab, Bb, tid);

        uint32_t sA = sbase + (it % NSTAGE) * STAGE;
        compute_chunk(sA + aOff, sA + TILE_B + bOff, acc);
    }
    __syncthreads();

    // epilogue: tanh(acc+bias) -> smem h tile
    float* hs = (float*)smem;
#pragma unroll
    for (int mf = 0; mf < 2; mf++) {
#pragma unroll
        for (int half = 0; half < 2; half++) {
            int r = wm + mf * 16 + (lid >> 2) + half * 8;
            const float* brow = bias + (size_t)(bm + r) * D + bn + wn;
            float* hrow = hs + r * HST + wn;
#pragma unroll
            for (int nf = 0; nf < 8; nf++) {
                int col = nf * 8 + 2 * (lid & 3);
                float2 bv = *(const float2*)(brow + col);
                hrow[col] = tanhf(acc[mf][nf][half * 2 + 0] + bv.x);
                hrow[col + 1] = tanhf(acc[mf][nf][half * 2 + 1] + bv.y);
            }
        }
    }
    __syncthreads();

    // fused child-combine -> Anext columns [bn, bn+128)
    {
        int p = tid >> 3;
        int g = tid & 7;
        int pg = (bm >> 2) + p;
        const float* h0 = hs + (4 * p + 0) * HST;
        const float* h1 = hs + (4 * p + 1) * HST;
        const float* h2 = hs + (4 * p + 2) * HST;
        const float* h3 = hs + (4 * p + 3) * HST;
        __nv_bfloat16* arow = Anext + (size_t)pg * KA;
#pragma unroll
        for (int i = 0; i < 2; i++) {
            int c0 = g * 16 + i * 8;
            __nv_bfloat16 lh[8], ll[8], rh[8], rl[8];
#pragma unroll
            for (int j = 0; j < 8; j++) {
                float a = h0[c0 + j], b = h1[c0 + j], c = h2[c0 + j], d = h3[c0 + j];
                float lv = a + (2.f/3.f) * b + (1.f/3.f) * c;
                float rv = (1.f/3.f) * b + (2.f/3.f) * c + d;
                split_bf16(lv, lh[j], ll[j]);
                split_bf16(rv, rh[j], rl[j]);
            }
            int cL = bn + c0;
            *(uint4*)(arow + cL) = *(const uint4*)lh;
            *(uint4*)(arow + 512 + cL) = *(const uint4*)ll;
            *(uint4*)(arow + 256 + cL) = *(const uint4*)rh;
            *(uint4*)(arow + 768 + cL) = *(const uint4*)rl;
        }
    }
}

// ---------------- split-K partial GEMM (l=6..4) ----------------
__global__ void __launch_bounds__(256, 2)
gemm_partial_kernel(const __nv_bfloat16* __restrict__ A,
                    const __nv_bfloat16* __restrict__ B,
                    float* __restrict__ P, int M, int cnt) {
    extern __shared__ __align__(128) char smem[];
    const uint32_t sbase = smem_u32(smem);
    const int tid = threadIdx.x;
    const int wid = tid >> 5;
    const int lid = tid & 31;
    const int bn = blockIdx.x * 128;
    const int bm = blockIdx.y * 128;
    const int c0 = blockIdx.z * cnt;

    const char* Ab = (const char*)A + (size_t)bm * ROWA;
    const char* Bb = (const char*)B + (size_t)bn * ROWBB;
    float* Pb = P + ((size_t)blockIdx.z * M + bm) * D + bn;

    float acc[2][8][4];
#pragma unroll
    for (int mf = 0; mf < 2; mf++)
#pragma unroll
        for (int nf = 0; nf < 8; nf++)
#pragma unroll
            for (int q = 0; q < 4; q++) acc[mf][nf][q] = 0.0f;

    const int wm = (wid & 3) * 32;
    const int wn = (wid >> 2) * 64;
    const uint32_t aOff = (uint32_t)(wm + (lid & 7) + ((lid & 8) ? 8 : 0)) * SROW +
                          ((lid & 16) ? 16 : 0);
    const uint32_t bOff = (uint32_t)(wn + (lid & 7) + ((lid & 16) ? 8 : 0)) * SROW +
                          ((lid & 8) ? 16 : 0);

    load_stage_g(sbase, 0, c0, Ab, Bb, tid);
    if (cnt > 1) load_stage_g(sbase, 1, c0 + 1, Ab, Bb, tid);

    for (int i = 0; i < cnt; i++) {
        if (i + 2 < cnt) {
            asm volatile("cp.async.wait_group 1;" ::: "memory");
        } else {
            asm volatile("cp.async.wait_group 0;" ::: "memory");
        }
        __syncthreads();
        if (i + 2 < cnt)
            load_stage_g(sbase, (i + 2) % NSTAGE, c0 + i + 2, Ab, Bb, tid);

        uint32_t sA = sbase + (i % NSTAGE) * STAGE;
        compute_chunk(sA + aOff, sA + TILE_B + bOff, acc);
    }

#pragma unroll
    for (int mf = 0; mf < 2; mf++) {
#pragma unroll
        for (int half = 0; half < 2; half++) {
            int r = wm + mf * 16 + (lid >> 2) + half * 8;
            float* prow = Pb + (size_t)r * D + wn;
#pragma unroll
            for (int nf = 0; nf < 8; nf++) {
                int col = nf * 8 + 2 * (lid & 3);
                float2 o;
                o.x = acc[mf][nf][half * 2 + 0];
                o.y = acc[mf][nf][half * 2 + 1];
                *(float2*)(prow + col) = o;
            }
        }
    }
}

// ---------------- epilogue: sum splits + bias + tanh + combine + split ----------------
__global__ void __launch_bounds__(256)
epilogue_combine_kernel(const float* __restrict__ P, int S,
                        const float* __restrict__ bias,
                        __nv_bfloat16* __restrict__ Anext,
                        float* __restrict__ hout, int M) {
    int idx = blockIdx.x * blockDim.x + threadIdx.x;
    int nPar = M >> 2;
    if (idx >= nPar * 64) return;
    int p = idx >> 6;
    int q = idx & 63;

    float4 h[4];
#pragma unroll
    for (int j = 0; j < 4; j++) {
        int row = 4 * p + j;
        float4 sum = *(const float4*)(P + (size_t)row * D + q * 4);
        for (int s = 1; s < S; s++) {
            float4 t = *(const float4*)(P + ((size_t)s * M + row) * D + q * 4);
            sum.x += t.x; sum.y += t.y; sum.z += t.z; sum.w += t.w;
        }
        float4 bv = *(const float4*)(bias + (size_t)row * D + q * 4);
        h[j].x = tanhf(sum.x + bv.x);
        h[j].y = tanhf(sum.y + bv.y);
        h[j].z = tanhf(sum.z + bv.z);
        h[j].w = tanhf(sum.w + bv.w);
        if (hout) *(float4*)(hout + (size_t)row * D + q * 4) = h[j];
    }

    if (Anext) {
        float4 uL, uR;
        uL.x = h[0].x + (2.f/3.f) * h[1].x + (1.f/3.f) * h[2].x;
        uL.y = h[0].y + (2.f/3.f) * h[1].y + (1.f/3.f) * h[2].y;
        uL.z = h[0].z + (2.f/3.f) * h[1].z + (1.f/3.f) * h[2].z;
        uL.w = h[0].w + (2.f/3.f) * h[1].w + (1.f/3.f) * h[2].w;
        uR.x = (1.f/3.f) * h[1].x + (2.f/3.f) * h[2].x + h[3].x;
        uR.y = (1.f/3.f) * h[1].y + (2.f/3.f) * h[2].y + h[3].y;
        uR.z = (1.f/3.f) * h[1].z + (2.f/3.f) * h[2].z + h[3].z;
        uR.w = (1.f/3.f) * h[1].w + (2.f/3.f) * h[2].w + h[3].w;

        __nv_bfloat16 lh[4], ll[4], rh[4], rl[4];
        split_bf16(uL.x, lh[0], ll[0]);
        split_bf16(uL.y, lh[1], ll[1]);
        split_bf16(uL.z, lh[2], ll[2]);
        split_bf16(uL.w, lh[3], ll[3]);
        split_bf16(uR.x, rh[0], rl[0]);
        split_bf16(uR.y, rh[1], rl[1]);
        split_bf16(uR.z, rh[2], rl[2]);
        split_bf16(uR.w, rh[3], rl[3]);

        __nv_bfloat16* arow = Anext + (size_t)p * KA + q * 4;
        *(uint2*)(arow)       = *(const uint2*)lh;
        *(uint2*)(arow + 256) = *(const uint2*)rh;
        *(uint2*)(arow + 512) = *(const uint2*)ll;
        *(uint2*)(arow + 768) = *(const uint2*)rl;
    }
}

// ---------------- small levels (M<=64): fp32 warp-per-output ----------------
__global__ void __launch_bounds__(256)
small_level_kernel(const float* __restrict__ hprev,
                   const float* __restrict__ Wl,
                   const float* __restrict__ Wr,
                   const float* __restrict__ bias,
                   float* __restrict__ hout, int Mout) {
    int gw = (blockIdx.x * blockDim.x + threadIdx.x) >> 5;
    int lid = threadIdx.x & 31;
    if (gw >= Mout * D) return;
    int p = gw >> 8;
    int n = gw & 255;
    const float* h0 = hprev + (size_t)(4 * p) * D;
    const float* wl = Wl + (size_t)n * D;
    const float* wr = Wr + (size_t)n * D;
    float acc = 0.f;
#pragma unroll
    for (int i = 0; i < 8; i++) {
        int k = lid + i * 32;
        float a = h0[k], b = h0[D + k], c = h0[2 * D + k], d = h0[3 * D + k];
        float uL = a + (2.f/3.f) * b + (1.f/3.f) * c;
        float uR = (1.f/3.f) * b + (2.f/3.f) * c + d;
        acc = fmaf(uL, wl[k], acc);
        acc = fmaf(uR, wr[k], acc);
    }
#pragma unroll
    for (int o = 16; o; o >>= 1) acc += __shfl_xor_sync(0xffffffffu, acc, o);
    if (lid == 0)
        hout[(size_t)p * D + n] = tanhf(acc + bias[(size_t)p * D + n]);
}

// ---------------- launcher ----------------
extern "C" void kernel_launch(void* const* d_in, const int* in_sizes, int n_in,
                              void* d_out, int out_size) {
    const float* vectors = (const float*)d_in[0];
    const float* Wl = (const float*)d_in[1];
    const float* Wr = (const float*)d_in[2];
    float* out = (float*)d_out;

    __nv_bfloat16 *Acat0, *Acat1, *Bcat;
    float *part, *hsA, *hsB;
    cudaGetSymbolAddress((void**)&Acat0, g_Acat0);
    cudaGetSymbolAddress((void**)&Acat1, g_Acat1);
    cudaGetSymbolAddress((void**)&Bcat, g_Bcat);
    cudaGetSymbolAddress((void**)&part, g_part);
    cudaGetSymbolAddress((void**)&hsA, g_hsA);
    cudaGetSymbolAddress((void**)&hsB, g_hsB);

    cudaFuncSetAttribute(gemm_fused_l7,
                         cudaFuncAttributeMaxDynamicSharedMemorySize, SMEM_TOTAL);
    cudaFuncSetAttribute(gemm_fused_l7,
                         cudaFuncAttributePreferredSharedMemoryCarveout, 100);
    cudaFuncSetAttribute(gemm_partial_kernel,
                         cudaFuncAttributeMaxDynamicSharedMemorySize, SMEM_TOTAL);
    cudaFuncSetAttribute(gemm_partial_kernel,
                         cudaFuncAttributePreferredSharedMemoryCarveout, 100);

    prep_w_kernel<<<(D * 512 + 255) / 256, 256>>>(Wl, Wr, Bcat);

    static const int offs[9] = {0, 1, 5, 21, 85, 341, 1365, 5461, 21845};

    const float* leaves = vectors + (size_t)offs[8] * D;
    leaf_reduce_kernel<<<(16384 * 128 + 255) / 256, 256>>>(leaves, Acat0, 16384);

    // l=7: fused full-K GEMM, Acat0 -> Acat1
    {
        dim3 grid(2, 128);
        gemm_fused_l7<<<grid, 256, SMEM_TOTAL>>>(
            Acat0, Bcat, vectors + (size_t)offs[7] * D, Acat1, 16384);
    }

    // l=6..4: split-K
    static const int SPLITS[8] = {0, 0, 0, 0, 12, 8, 4, 0};
    __nv_bfloat16* Ain = Acat1;
    for (int l = 6; l >= 4; --l) {
        int M = 1 << (2 * l);
        int S = SPLITS[l];
        int cnt = NCHUNK / S;
        __nv_bfloat16* Anext =
            (l > 4) ? ((Ain == Acat0) ? Acat1 : Acat0) : (__nv_bfloat16*)nullptr;
        float* hout = (l == 4) ? hsA : nullptr;
        const float* bias = vectors + (size_t)offs[l] * D;

        dim3 grid(2, M / 128, S);
        gemm_partial_kernel<<<grid, 256, SMEM_TOTAL>>>(Ain, Bcat, part, M, cnt);

        int nthr = (M / 4) * 64;
        epilogue_combine_kernel<<<(nthr + 255) / 256, 256>>>(part, S, bias, Anext, hout, M);

        Ain = Anext;
    }

    // l=3..0: fp32 SIMT
    const float* hin = hsA;
    for (int l = 3; l >= 0; --l) {
        int M = 1 << (2 * l);
        float* hout = (l == 0) ? out : ((l & 1) ? hsB : hsA);
        const float* bias = vectors + (size_t)offs[l] * D;
        int nwarps = M * D;
        small_level_kernel<<<(nwarps * 32 + 255) / 256, 256>>>(hin, Wl, Wr, bias, hout, M);
        hin = hout;
    }
}

// round 10
// speedup vs baseline: 3.1462x; 1.0098x over previous
#include <cuda_runtime.h>
#include <cuda_bf16.h>
#include <cstdint>
#include <math.h>

// CBTree B=4, L=9, d=256.
// l=7: full-K fused GEMM (tanh+combine epilogue -> Anext). l=6..4: split-K
// partial GEMM + epilogue kernel. l=3..0: fp32 SIMT warp-per-output.
// Split-bf16: A=[hi|lo] (K=1024), B=[hi|lo]; 24 chunk passes hi*hi, lo*hi, hi*lo.
// GEMM CTA: 512 threads, 16 warps 4(m)x4(n), warp tile 32x32 (occupancy-first).

#define D 256
#define KA 1024
#define ROWA 2048
#define ROWBB 2048
#define NCHUNK 24
#define SROW 144
#define TILE_B (128 * SROW)
#define STAGE (2 * TILE_B)            // 36864
#define NSTAGE 3
#define SMEM_TOTAL (NSTAGE * STAGE)   // 110592 (2 CTAs/SM: 221KB <= 228KB)
#define HST 132
#define NTHR 512

// ---------------- static device scratch ----------------
__device__ __nv_bfloat16 g_Acat0[16384 * 1024];
__device__ __nv_bfloat16 g_Acat1[16384 * 1024];
__device__ __nv_bfloat16 g_Bcat[256 * 1024];
__device__ float g_part[16384 * 256];
__device__ float g_hsA[256 * 256];
__device__ float g_hsB[256 * 256];

// ---------------- helpers ----------------
__device__ __forceinline__ uint32_t smem_u32(const void* p) {
    uint32_t a;
    asm("{ .reg .u64 t; cvta.to.shared.u64 t, %1; cvt.u32.u64 %0, t; }" : "=r"(a) : "l"(p));
    return a;
}
__device__ __forceinline__ void cp_async16(uint32_t dst, const void* src) {
    asm volatile("cp.async.cg.shared.global [%0], [%1], 16;" :: "r"(dst), "l"(src));
}
#define CP_COMMIT() asm volatile("cp.async.commit_group;" ::: "memory")

__device__ __forceinline__ void ldm_x4(uint32_t* r, uint32_t addr) {
    asm volatile("ldmatrix.sync.aligned.m8n8.x4.shared.b16 {%0,%1,%2,%3}, [%4];"
                 : "=r"(r[0]), "=r"(r[1]), "=r"(r[2]), "=r"(r[3]) : "r"(addr));
}
__device__ __forceinline__ void mma_bf16(float* c, const uint32_t* a, uint32_t b0, uint32_t b1) {
    asm volatile("mma.sync.aligned.m16n8k16.row.col.f32.bf16.bf16.f32 "
                 "{%0,%1,%2,%3}, {%4,%5,%6,%7}, {%8,%9}, {%0,%1,%2,%3};"
                 : "+f"(c[0]), "+f"(c[1]), "+f"(c[2]), "+f"(c[3])
                 : "r"(a[0]), "r"(a[1]), "r"(a[2]), "r"(a[3]), "r"(b0), "r"(b1));
}
__device__ __forceinline__ void split_bf16(float v, __nv_bfloat16& hi, __nv_bfloat16& lo) {
    hi = __float2bfloat16_rn(v);
    lo = __float2bfloat16_rn(v - __bfloat162float(hi));
}

// Per-chunk compute for 32x32 warp tile: 4 ldm_x4 + 8 MMA per kk.
// B fragment layout (proven in R3-R8): lanes (lid&7)+((lid&16)?8:0) pick the n-row,
// (lid&8) picks the k-halfword -> regs [0],[1] = n0-7 k-pair; [2],[3] = n8-15.
__device__ __forceinline__ void compute_chunk(uint32_t aAddr, uint32_t bAddr,
                                              float acc[2][4][4]) {
#pragma unroll
    for (int kk = 0; kk < 4; kk++) {
        uint32_t a0[4], a1[4], b0[4], b1[4];
        ldm_x4(a0, aAddr + kk * 32);
        ldm_x4(a1, aAddr + 16 * SROW + kk * 32);
        ldm_x4(b0, bAddr + kk * 32);
        ldm_x4(b1, bAddr + 16 * SROW + kk * 32);
        mma_bf16(acc[0][0], a0, b0[0], b0[1]);
        mma_bf16(acc[0][1], a0, b0[2], b0[3]);
        mma_bf16(acc[0][2], a0, b1[0], b1[1]);
        mma_bf16(acc[0][3], a0, b1[2], b1[3]);
        mma_bf16(acc[1][0], a1, b0[0], b0[1]);
        mma_bf16(acc[1][1], a1, b0[2], b0[3]);
        mma_bf16(acc[1][2], a1, b1[0], b1[1]);
        mma_bf16(acc[1][3], a1, b1[2], b1[3]);
    }
}

// ---------------- prep: Bcat = [hi(W) | lo(W)] ----------------
__global__ void prep_w_kernel(const float* __restrict__ Wl,
                              const float* __restrict__ Wr,
                              __nv_bfloat16* __restrict__ Bcat) {
    int idx = blockIdx.x * blockDim.x + threadIdx.x;
    if (idx >= D * 512) return;
    int n = idx >> 9;
    int k = idx & 511;
    float w = (k < D) ? Wl[n * D + k] : Wr[n * D + (k - D)];
    __nv_bfloat16 hi, lo;
    split_bf16(w, hi, lo);
    Bcat[(size_t)n * KA + k] = hi;
    Bcat[(size_t)n * KA + 512 + k] = lo;
}

// ---------------- leaf reduce -> Acat [hi|lo] ----------------
__global__ void leaf_reduce_kernel(const float* __restrict__ h,
                                   __nv_bfloat16* __restrict__ Acat,
                                   int n_par) {
    int idx = blockIdx.x * blockDim.x + threadIdx.x;
    if (idx >= n_par * 128) return;
    int p = idx >> 7;
    int q = idx & 127;
    const float4* hp = (const float4*)(h + (size_t)p * 1024);
    float4 v;
    if (q < 64) {
        float4 a = hp[q], b = hp[64 + q], c = hp[128 + q];
        v.x = a.x + (2.f/3.f) * b.x + (1.f/3.f) * c.x;
        v.y = a.y + (2.f/3.f) * b.y + (1.f/3.f) * c.y;
        v.z = a.z + (2.f/3.f) * b.z + (1.f/3.f) * c.z;
        v.w = a.w + (2.f/3.f) * b.w + (1.f/3.f) * c.w;
    } else {
        int q2 = q - 64;
        float4 b = hp[64 + q2], c = hp[128 + q2], d = hp[192 + q2];
        v.x = (1.f/3.f) * b.x + (2.f/3.f) * c.x + d.x;
        v.y = (1.f/3.f) * b.y + (2.f/3.f) * c.y + d.y;
        v.z = (1.f/3.f) * b.z + (2.f/3.f) * c.z + d.z;
        v.w = (1.f/3.f) * b.w + (2.f/3.f) * c.w + d.w;
    }
    __nv_bfloat16 hi[4], lo[4];
    split_bf16(v.x, hi[0], lo[0]);
    split_bf16(v.y, hi[1], lo[1]);
    split_bf16(v.z, hi[2], lo[2]);
    split_bf16(v.w, hi[3], lo[3]);
    __nv_bfloat16* arow = Acat + (size_t)p * KA + q * 4;
    *(uint2*)arow = *(const uint2*)hi;
    *(uint2*)(arow + 512) = *(const uint2*)lo;
}

// ======== stage loader (512 threads) ========
__device__ __forceinline__ void load_stage_g(uint32_t sbase, int slot, int it,
                                             const char* Ab, const char* Bb, int tid) {
    int aCh = (it < 16) ? it : it - 16;
    int bCh = (it < 8) ? it : it - 8;
    uint32_t sA = sbase + slot * STAGE;
    uint32_t sB = sA + TILE_B;
#pragma unroll
    for (int i = 0; i < 2; i++) {
        int id = i * NTHR + tid;
        int r = id >> 3, c = id & 7;
        cp_async16(sA + r * SROW + c * 16, Ab + (size_t)r * ROWA + aCh * 128 + c * 16);
    }
#pragma unroll
    for (int i = 0; i < 2; i++) {
        int id = i * NTHR + tid;
        int r = id >> 3, c = id & 7;
        cp_async16(sB + r * SROW + c * 16, Bb + (size_t)r * ROWBB + bCh * 128 + c * 16);
    }
    CP_COMMIT();
}

// ---------------- l=7: full-K GEMM + fused tanh/combine epilogue ----------------
__global__ void __launch_bounds__(NTHR, 2)
gemm_fused_l7(const __nv_bfloat16* __restrict__ A,
              const __nv_bfloat16* __restrict__ B,
              const float* __restrict__ bias,
              __nv_bfloat16* __restrict__ Anext, int M) {
    extern __shared__ __align__(128) char smem[];
    const uint32_t sbase = smem_u32(smem);
    const int tid = threadIdx.x;
    const int wid = tid >> 5;
    const int lid = tid & 31;
    const int bn = blockIdx.x * 128;
    const int bm = blockIdx.y * 128;

    const char* Ab = (const char*)A + (size_t)bm * ROWA;
    const char* Bb = (const char*)B + (size_t)bn * ROWBB;

    float acc[2][4][4];
#pragma unroll
    for (int mf = 0; mf < 2; mf++)
#pragma unroll
        for (int nf = 0; nf < 4; nf++)
#pragma unroll
            for (int q = 0; q < 4; q++) acc[mf][nf][q] = 0.0f;

    const int wm = (wid & 3) * 32;
    const int wn = (wid >> 2) * 32;
    const uint32_t aOff = (uint32_t)(wm + (lid & 7) + ((lid & 8) ? 8 : 0)) * SROW +
                          ((lid & 16) ? 16 : 0);
    const uint32_t bOff = (uint32_t)(wn + (lid & 7) + ((lid & 16) ? 8 : 0)) * SROW +
                          ((lid & 8) ? 16 : 0);

    load_stage_g(sbase, 0, 0, Ab, Bb, tid);
    load_stage_g(sbase, 1, 1, Ab, Bb, tid);

    for (int it = 0; it < NCHUNK; it++) {
        if (it + 2 < NCHUNK) {
            asm volatile("cp.async.wait_group 1;" ::: "memory");
        } else {
            asm volatile("cp.async.wait_group 0;" ::: "memory");
        }
        __syncthreads();
        if (it + 2 < NCHUNK)
            load_stage_g(sbase, (it + 2) % NSTAGE, it + 2, Ab, Bb, tid);

        uint32_t sA = sbase + (it % NSTAGE) * STAGE;
        compute_chunk(sA + aOff, sA + TILE_B + bOff, acc);
    }
    __syncthreads();

    // epilogue: tanh(acc+bias) -> smem h tile
    float* hs = (float*)smem;
#pragma unroll
    for (int mf = 0; mf < 2; mf++) {
#pragma unroll
        for (int half = 0; half < 2; half++) {
            int r = wm + mf * 16 + (lid >> 2) + half * 8;
            const float* brow = bias + (size_t)(bm + r) * D + bn + wn;
            float* hrow = hs + r * HST + wn;
#pragma unroll
            for (int nf = 0; nf < 4; nf++) {
                int col = nf * 8 + 2 * (lid & 3);
                float2 bv = *(const float2*)(brow + col);
                hrow[col] = tanhf(acc[mf][nf][half * 2 + 0] + bv.x);
                hrow[col + 1] = tanhf(acc[mf][nf][half * 2 + 1] + bv.y);
            }
        }
    }
    __syncthreads();

    // fused child-combine -> Anext columns [bn, bn+128): 512 thr, 8 cols each
    {
        int p = tid >> 4;          // 0..31
        int g = tid & 15;          // 0..15 -> 8-col group
        int pg = (bm >> 2) + p;
        const float* h0 = hs + (4 * p + 0) * HST;
        const float* h1 = hs + (4 * p + 1) * HST;
        const float* h2 = hs + (4 * p + 2) * HST;
        const float* h3 = hs + (4 * p + 3) * HST;
        __nv_bfloat16* arow = Anext + (size_t)pg * KA;
        int c0 = g * 8;
        __nv_bfloat16 lh[8], ll[8], rh[8], rl[8];
#pragma unroll
        for (int j = 0; j < 8; j++) {
            float a = h0[c0 + j], b = h1[c0 + j], c = h2[c0 + j], d = h3[c0 + j];
            float lv = a + (2.f/3.f) * b + (1.f/3.f) * c;
            float rv = (1.f/3.f) * b + (2.f/3.f) * c + d;
            split_bf16(lv, lh[j], ll[j]);
            split_bf16(rv, rh[j], rl[j]);
        }
        int cL = bn + c0;
        *(uint4*)(arow + cL) = *(const uint4*)lh;
        *(uint4*)(arow + 512 + cL) = *(const uint4*)ll;
        *(uint4*)(arow + 256 + cL) = *(const uint4*)rh;
        *(uint4*)(arow + 768 + cL) = *(const uint4*)rl;
    }
}

// ---------------- split-K partial GEMM (l=6..4) ----------------
__global__ void __launch_bounds__(NTHR, 2)
gemm_partial_kernel(const __nv_bfloat16* __restrict__ A,
                    const __nv_bfloat16* __restrict__ B,
                    float* __restrict__ P, int M, int cnt) {
    extern __shared__ __align__(128) char smem[];
    const uint32_t sbase = smem_u32(smem);
    const int tid = threadIdx.x;
    const int wid = tid >> 5;
    const int lid = tid & 31;
    const int bn = blockIdx.x * 128;
    const int bm = blockIdx.y * 128;
    const int c0 = blockIdx.z * cnt;

    const char* Ab = (const char*)A + (size_t)bm * ROWA;
    const char* Bb = (const char*)B + (size_t)bn * ROWBB;
    float* Pb = P + ((size_t)blockIdx.z * M + bm) * D + bn;

    float acc[2][4][4];
#pragma unroll
    for (int mf = 0; mf < 2; mf++)
#pragma unroll
        for (int nf = 0; nf < 4; nf++)
#pragma unroll
            for (int q = 0; q < 4; q++) acc[mf][nf][q] = 0.0f;

    const int wm = (wid & 3) * 32;
    const int wn = (wid >> 2) * 32;
    const uint32_t aOff = (uint32_t)(wm + (lid & 7) + ((lid & 8) ? 8 : 0)) * SROW +
                          ((lid & 16) ? 16 : 0);
    const uint32_t bOff = (uint32_t)(wn + (lid & 7) + ((lid & 16) ? 8 : 0)) * SROW +
                          ((lid & 8) ? 16 : 0);

    load_stage_g(sbase, 0, c0, Ab, Bb, tid);
    if (cnt > 1) load_stage_g(sbase, 1, c0 + 1, Ab, Bb, tid);

    for (int i = 0; i < cnt; i++) {
        if (i + 2 < cnt) {
            asm volatile("cp.async.wait_group 1;" ::: "memory");
        } else {
            asm volatile("cp.async.wait_group 0;" ::: "memory");
        }
        __syncthreads();
        if (i + 2 < cnt)
            load_stage_g(sbase, (i + 2) % NSTAGE, c0 + i + 2, Ab, Bb, tid);

        uint32_t sA = sbase + (i % NSTAGE) * STAGE;
        compute_chunk(sA + aOff, sA + TILE_B + bOff, acc);
    }

#pragma unroll
    for (int mf = 0; mf < 2; mf++) {
#pragma unroll
        for (int half = 0; half < 2; half++) {
            int r = wm + mf * 16 + (lid >> 2) + half * 8;
            float* prow = Pb + (size_t)r * D + wn;
#pragma unroll
            for (int nf = 0; nf < 4; nf++) {
                int col = nf * 8 + 2 * (lid & 3);
                float2 o;
                o.x = acc[mf][nf][half * 2 + 0];
                o.y = acc[mf][nf][half * 2 + 1];
                *(float2*)(prow + col) = o;
            }
        }
    }
}

// ---------------- epilogue: sum splits + bias + tanh + combine + split ----------------
__global__ void __launch_bounds__(256)
epilogue_combine_kernel(const float* __restrict__ P, int S,
                        const float* __restrict__ bias,
                        __nv_bfloat16* __restrict__ Anext,
                        float* __restrict__ hout, int M) {
    int idx = blockIdx.x * blockDim.x + threadIdx.x;
    int nPar = M >> 2;
    if (idx >= nPar * 64) return;
    int p = idx >> 6;
    int q = idx & 63;

    float4 h[4];
#pragma unroll
    for (int j = 0; j < 4; j++) {
        int row = 4 * p + j;
        float4 sum = *(const float4*)(P + (size_t)row * D + q * 4);
        for (int s = 1; s < S; s++) {
            float4 t = *(const float4*)(P + ((size_t)s * M + row) * D + q * 4);
            sum.x += t.x; sum.y += t.y; sum.z += t.z; sum.w += t.w;
        }
        float4 bv = *(const float4*)(bias + (size_t)row * D + q * 4);
        h[j].x = tanhf(sum.x + bv.x);
        h[j].y = tanhf(sum.y + bv.y);
        h[j].z = tanhf(sum.z + bv.z);
        h[j].w = tanhf(sum.w + bv.w);
        if (hout) *(float4*)(hout + (size_t)row * D + q * 4) = h[j];
    }

    if (Anext) {
        float4 uL, uR;
        uL.x = h[0].x + (2.f/3.f) * h[1].x + (1.f/3.f) * h[2].x;
        uL.y = h[0].y + (2.f/3.f) * h[1].y + (1.f/3.f) * h[2].y;
        uL.z = h[0].z + (2.f/3.f) * h[1].z + (1.f/3.f) * h[2].z;
        uL.w = h[0].w + (2.f/3.f) * h[1].w + (1.f/3.f) * h[2].w;
        uR.x = (1.f/3.f) * h[1].x + (2.f/3.f) * h[2].x + h[3].x;
        uR.y = (1.f/3.f) * h[1].y + (2.f/3.f) * h[2].y + h[3].y;
        uR.z = (1.f/3.f) * h[1].z + (2.f/3.f) * h[2].z + h[3].z;
        uR.w = (1.f/3.f) * h[1].w + (2.f/3.f) * h[2].w + h[3].w;

        __nv_bfloat16 lh[4], ll[4], rh[4], rl[4];
        split_bf16(uL.x, lh[0], ll[0]);
        split_bf16(uL.y, lh[1], ll[1]);
        split_bf16(uL.z, lh[2], ll[2]);
        split_bf16(uL.w, lh[3], ll[3]);
        split_bf16(uR.x, rh[0], rl[0]);
        split_bf16(uR.y, rh[1], rl[1]);
        split_bf16(uR.z, rh[2], rl[2]);
        split_bf16(uR.w, rh[3], rl[3]);

        __nv_bfloat16* arow = Anext + (size_t)p * KA + q * 4;
        *(uint2*)(arow)       = *(const uint2*)lh;
        *(uint2*)(arow + 256) = *(const uint2*)rh;
        *(uint2*)(arow + 512) = *(const uint2*)ll;
        *(uint2*)(arow + 768) = *(const uint2*)rl;
    }
}

// ---------------- small levels (M<=64): fp32 warp-per-output ----------------
__global__ void __launch_bounds__(256)
small_level_kernel(const float* __restrict__ hprev,
                   const float* __restrict__ Wl,
                   const float* __restrict__ Wr,
                   const float* __restrict__ bias,
                   float* __restrict__ hout, int Mout) {
    int gw = (blockIdx.x * blockDim.x + threadIdx.x) >> 5;
    int lid = threadIdx.x & 31;
    if (gw >= Mout * D) return;
    int p = gw >> 8;
    int n = gw & 255;
    const float* h0 = hprev + (size_t)(4 * p) * D;
    const float* wl = Wl + (size_t)n * D;
    const float* wr = Wr + (size_t)n * D;
    float acc = 0.f;
#pragma unroll
    for (int i = 0; i < 8; i++) {
        int k = lid + i * 32;
        float a = h0[k], b = h0[D + k], c = h0[2 * D + k], d = h0[3 * D + k];
        float uL = a + (2.f/3.f) * b + (1.f/3.f) * c;
        float uR = (1.f/3.f) * b + (2.f/3.f) * c + d;
        acc = fmaf(uL, wl[k], acc);
        acc = fmaf(uR, wr[k], acc);
    }
#pragma unroll
    for (int o = 16; o; o >>= 1) acc += __shfl_xor_sync(0xffffffffu, acc, o);
    if (lid == 0)
        hout[(size_t)p * D + n] = tanhf(acc + bias[(size_t)p * D + n]);
}

// ---------------- launcher ----------------
extern "C" void kernel_launch(void* const* d_in, const int* in_sizes, int n_in,
                              void* d_out, int out_size) {
    const float* vectors = (const float*)d_in[0];
    const float* Wl = (const float*)d_in[1];
    const float* Wr = (const float*)d_in[2];
    float* out = (float*)d_out;

    __nv_bfloat16 *Acat0, *Acat1, *Bcat;
    float *part, *hsA, *hsB;
    cudaGetSymbolAddress((void**)&Acat0, g_Acat0);
    cudaGetSymbolAddress((void**)&Acat1, g_Acat1);
    cudaGetSymbolAddress((void**)&Bcat, g_Bcat);
    cudaGetSymbolAddress((void**)&part, g_part);
    cudaGetSymbolAddress((void**)&hsA, g_hsA);
    cudaGetSymbolAddress((void**)&hsB, g_hsB);

    cudaFuncSetAttribute(gemm_fused_l7,
                         cudaFuncAttributeMaxDynamicSharedMemorySize, SMEM_TOTAL);
    cudaFuncSetAttribute(gemm_fused_l7,
                         cudaFuncAttributePreferredSharedMemoryCarveout, 100);
    cudaFuncSetAttribute(gemm_partial_kernel,
                         cudaFuncAttributeMaxDynamicSharedMemorySize, SMEM_TOTAL);
    cudaFuncSetAttribute(gemm_partial_kernel,
                         cudaFuncAttributePreferredSharedMemoryCarveout, 100);

    prep_w_kernel<<<(D * 512 + 255) / 256, 256>>>(Wl, Wr, Bcat);

    static const int offs[9] = {0, 1, 5, 21, 85, 341, 1365, 5461, 21845};

    const float* leaves = vectors + (size_t)offs[8] * D;
    leaf_reduce_kernel<<<(16384 * 128 + 255) / 256, 256>>>(leaves, Acat0, 16384);

    // l=7: fused full-K GEMM, Acat0 -> Acat1
    {
        dim3 grid(2, 128);
        gemm_fused_l7<<<grid, NTHR, SMEM_TOTAL>>>(
            Acat0, Bcat, vectors + (size_t)offs[7] * D, Acat1, 16384);
    }

    // l=6..4: split-K
    static const int SPLITS[8] = {0, 0, 0, 0, 12, 8, 4, 0};
    __nv_bfloat16* Ain = Acat1;
    for (int l = 6; l >= 4; --l) {
        int M = 1 << (2 * l);
        int S = SPLITS[l];
        int cnt = NCHUNK / S;
        __nv_bfloat16* Anext =
            (l > 4) ? ((Ain == Acat0) ? Acat1 : Acat0) : (__nv_bfloat16*)nullptr;
        float* hout = (l == 4) ? hsA : nullptr;
        const float* bias = vectors + (size_t)offs[l] * D;

        dim3 grid(2, M / 128, S);
        gemm_partial_kernel<<<grid, NTHR, SMEM_TOTAL>>>(Ain, Bcat, part, M, cnt);

        int nthr = (M / 4) * 64;
        epilogue_combine_kernel<<<(nthr + 255) / 256, 256>>>(part, S, bias, Anext, hout, M);

        Ain = Anext;
    }

    // l=3..0: fp32 SIMT
    const float* hin = hsA;
    for (int l = 3; l >= 0; --l) {
        int M = 1 << (2 * l);
        float* hout = (l == 0) ? out : ((l & 1) ? hsB : hsA);
        const float* bias = vectors + (size_t)offs[l] * D;
        int nwarps = M * D;
        small_level_kernel<<<(nwarps * 32 + 255) / 256, 256>>>(hin, Wl, Wr, bias, hout, M);
        hin = hout;
    }
}

// round 11
// speedup vs baseline: 3.5987x; 1.1438x over previous
#include <cuda_runtime.h>
#include <cuda_fp16.h>
#include <cstdint>
#include <math.h>

// CBTree B=4, L=9, d=256.
// Split-fp16 2-term: A=[hi(u)|lo(u)] fp16 (K=1024), B=hi(W) fp16 (K=512).
// C = (a_hi + a_lo) . b_hi  -> 16 chunk passes of 64 (it 0-7 hi, 8-15 lo; b = it&7).
// l=7: full-K fused GEMM (tanh+combine -> Anext). l=6..4: split-K + epilogue.
// l=3..0: fp32 SIMT warp-per-output.

#define D 256
#define KA 1024
#define ROWA 2048        // A row bytes (1024 fp16)
#define ROWBB 1024       // B row bytes (512 fp16)
#define NCHUNK 16
#define SROW 144
#define TILE_B (128 * SROW)
#define STAGE (2 * TILE_B)            // 36864
#define NSTAGE 3
#define SMEM_TOTAL (NSTAGE * STAGE)   // 110592 (2 CTAs/SM)
#define HST 132
#define NTHR 512

// ---------------- static device scratch ----------------
__device__ __half g_Acat0[16384 * 1024];
__device__ __half g_Acat1[16384 * 1024];
__device__ __half g_Bcat[256 * 512];
__device__ float g_part[16384 * 256];
__device__ float g_hsA[256 * 256];
__device__ float g_hsB[256 * 256];

// ---------------- helpers ----------------
__device__ __forceinline__ uint32_t smem_u32(const void* p) {
    uint32_t a;
    asm("{ .reg .u64 t; cvta.to.shared.u64 t, %1; cvt.u32.u64 %0, t; }" : "=r"(a) : "l"(p));
    return a;
}
__device__ __forceinline__ void cp_async16(uint32_t dst, const void* src) {
    asm volatile("cp.async.cg.shared.global [%0], [%1], 16;" :: "r"(dst), "l"(src));
}
#define CP_COMMIT() asm volatile("cp.async.commit_group;" ::: "memory")

__device__ __forceinline__ void ldm_x4(uint32_t* r, uint32_t addr) {
    asm volatile("ldmatrix.sync.aligned.m8n8.x4.shared.b16 {%0,%1,%2,%3}, [%4];"
                 : "=r"(r[0]), "=r"(r[1]), "=r"(r[2]), "=r"(r[3]) : "r"(addr));
}
__device__ __forceinline__ void mma_f16(float* c, const uint32_t* a, uint32_t b0, uint32_t b1) {
    asm volatile("mma.sync.aligned.m16n8k16.row.col.f32.f16.f16.f32 "
                 "{%0,%1,%2,%3}, {%4,%5,%6,%7}, {%8,%9}, {%0,%1,%2,%3};"
                 : "+f"(c[0]), "+f"(c[1]), "+f"(c[2]), "+f"(c[3])
                 : "r"(a[0]), "r"(a[1]), "r"(a[2]), "r"(a[3]), "r"(b0), "r"(b1));
}
__device__ __forceinline__ void split_fp16(float v, __half& hi, __half& lo) {
    hi = __float2half_rn(v);
    lo = __float2half_rn(v - __half2float(hi));
}

// Per-chunk compute for 32x32 warp tile: 4 ldm_x4 + 8 MMA per kk.
__device__ __forceinline__ void compute_chunk(uint32_t aAddr, uint32_t bAddr,
                                              float acc[2][4][4]) {
#pragma unroll
    for (int kk = 0; kk < 4; kk++) {
        uint32_t a0[4], a1[4], b0[4], b1[4];
        ldm_x4(a0, aAddr + kk * 32);
        ldm_x4(a1, aAddr + 16 * SROW + kk * 32);
        ldm_x4(b0, bAddr + kk * 32);
        ldm_x4(b1, bAddr + 16 * SROW + kk * 32);
        mma_f16(acc[0][0], a0, b0[0], b0[1]);
        mma_f16(acc[0][1], a0, b0[2], b0[3]);
        mma_f16(acc[0][2], a0, b1[0], b1[1]);
        mma_f16(acc[0][3], a0, b1[2], b1[3]);
        mma_f16(acc[1][0], a1, b0[0], b0[1]);
        mma_f16(acc[1][1], a1, b0[2], b0[3]);
        mma_f16(acc[1][2], a1, b1[0], b1[1]);
        mma_f16(acc[1][3], a1, b1[2], b1[3]);
    }
}

// ---------------- prep: Bcat = hi(W) fp16 ----------------
__global__ void prep_w_kernel(const float* __restrict__ Wl,
                              const float* __restrict__ Wr,
                              __half* __restrict__ Bcat) {
    int idx = blockIdx.x * blockDim.x + threadIdx.x;
    if (idx >= D * 512) return;
    int n = idx >> 9;
    int k = idx & 511;
    float w = (k < D) ? Wl[n * D + k] : Wr[n * D + (k - D)];
    Bcat[(size_t)n * 512 + k] = __float2half_rn(w);
}

// ---------------- leaf reduce -> Acat [hi|lo] fp16 ----------------
__global__ void leaf_reduce_kernel(const float* __restrict__ h,
                                   __half* __restrict__ Acat,
                                   int n_par) {
    int idx = blockIdx.x * blockDim.x + threadIdx.x;
    if (idx >= n_par * 128) return;
    int p = idx >> 7;
    int q = idx & 127;
    const float4* hp = (const float4*)(h + (size_t)p * 1024);
    float4 v;
    if (q < 64) {
        float4 a = hp[q], b = hp[64 + q], c = hp[128 + q];
        v.x = a.x + (2.f/3.f) * b.x + (1.f/3.f) * c.x;
        v.y = a.y + (2.f/3.f) * b.y + (1.f/3.f) * c.y;
        v.z = a.z + (2.f/3.f) * b.z + (1.f/3.f) * c.z;
        v.w = a.w + (2.f/3.f) * b.w + (1.f/3.f) * c.w;
    } else {
        int q2 = q - 64;
        float4 b = hp[64 + q2], c = hp[128 + q2], d = hp[192 + q2];
        v.x = (1.f/3.f) * b.x + (2.f/3.f) * c.x + d.x;
        v.y = (1.f/3.f) * b.y + (2.f/3.f) * c.y + d.y;
        v.z = (1.f/3.f) * b.z + (2.f/3.f) * c.z + d.z;
        v.w = (1.f/3.f) * b.w + (2.f/3.f) * c.w + d.w;
    }
    __half hi[4], lo[4];
    split_fp16(v.x, hi[0], lo[0]);
    split_fp16(v.y, hi[1], lo[1]);
    split_fp16(v.z, hi[2], lo[2]);
    split_fp16(v.w, hi[3], lo[3]);
    __half* arow = Acat + (size_t)p * KA + q * 4;
    *(uint2*)arow = *(const uint2*)hi;
    *(uint2*)(arow + 512) = *(const uint2*)lo;
}

// ======== stage loader (512 threads) ========
// A chunk: aCh = it (16 chunks of 64 fp16 = 128B). B chunk: bCh = it & 7.
__device__ __forceinline__ void load_stage_g(uint32_t sbase, int slot, int it,
                                             const char* Ab, const char* Bb, int tid) {
    int aCh = it;
    int bCh = it & 7;
    uint32_t sA = sbase + slot * STAGE;
    uint32_t sB = sA + TILE_B;
#pragma unroll
    for (int i = 0; i < 2; i++) {
        int id = i * NTHR + tid;
        int r = id >> 3, c = id & 7;
        cp_async16(sA + r * SROW + c * 16, Ab + (size_t)r * ROWA + aCh * 128 + c * 16);
    }
#pragma unroll
    for (int i = 0; i < 2; i++) {
        int id = i * NTHR + tid;
        int r = id >> 3, c = id & 7;
        cp_async16(sB + r * SROW + c * 16, Bb + (size_t)r * ROWBB + bCh * 128 + c * 16);
    }
    CP_COMMIT();
}

// ---------------- l=7: full-K GEMM + fused tanh/combine epilogue ----------------
__global__ void __launch_bounds__(NTHR, 2)
gemm_fused_l7(const __half* __restrict__ A,
              const __half* __restrict__ B,
              const float* __restrict__ bias,
              __half* __restrict__ Anext, int M) {
    extern __shared__ __align__(128) char smem[];
    const uint32_t sbase = smem_u32(smem);
    const int tid = threadIdx.x;
    const int wid = tid >> 5;
    const int lid = tid & 31;
    const int bn = blockIdx.x * 128;
    const int bm = blockIdx.y * 128;

    const char* Ab = (const char*)A + (size_t)bm * ROWA;
    const char* Bb = (const char*)B + (size_t)bn * ROWBB;

    float acc[2][4][4];
#pragma unroll
    for (int mf = 0; mf < 2; mf++)
#pragma unroll
        for (int nf = 0; nf < 4; nf++)
#pragma unroll
            for (int q = 0; q < 4; q++) acc[mf][nf][q] = 0.0f;

    const int wm = (wid & 3) * 32;
    const int wn = (wid >> 2) * 32;
    const uint32_t aOff = (uint32_t)(wm + (lid & 7) + ((lid & 8) ? 8 : 0)) * SROW +
                          ((lid & 16) ? 16 : 0);
    const uint32_t bOff = (uint32_t)(wn + (lid & 7) + ((lid & 16) ? 8 : 0)) * SROW +
                          ((lid & 8) ? 16 : 0);

    load_stage_g(sbase, 0, 0, Ab, Bb, tid);
    load_stage_g(sbase, 1, 1, Ab, Bb, tid);

    for (int it = 0; it < NCHUNK; it++) {
        if (it + 2 < NCHUNK) {
            asm volatile("cp.async.wait_group 1;" ::: "memory");
        } else {
            asm volatile("cp.async.wait_group 0;" ::: "memory");
        }
        __syncthreads();
        if (it + 2 < NCHUNK)
            load_stage_g(sbase, (it + 2) % NSTAGE, it + 2, Ab, Bb, tid);

        uint32_t sA = sbase + (it % NSTAGE) * STAGE;
        compute_chunk(sA + aOff, sA + TILE_B + bOff, acc);
    }
    __syncthreads();

    // epilogue: tanh(acc+bias) -> smem h tile
    float* hs = (float*)smem;
#pragma unroll
    for (int mf = 0; mf < 2; mf++) {
#pragma unroll
        for (int half = 0; half < 2; half++) {
            int r = wm + mf * 16 + (lid >> 2) + half * 8;
            const float* brow = bias + (size_t)(bm + r) * D + bn + wn;
            float* hrow = hs + r * HST + wn;
#pragma unroll
            for (int nf = 0; nf < 4; nf++) {
                int col = nf * 8 + 2 * (lid & 3);
                float2 bv = *(const float2*)(brow + col);
                hrow[col] = tanhf(acc[mf][nf][half * 2 + 0] + bv.x);
                hrow[col + 1] = tanhf(acc[mf][nf][half * 2 + 1] + bv.y);
            }
        }
    }
    __syncthreads();

    // fused child-combine -> Anext columns [bn, bn+128): 512 thr, 8 cols each
    {
        int p = tid >> 4;          // 0..31
        int g = tid & 15;          // 0..15 -> 8-col group
        int pg = (bm >> 2) + p;
        const float* h0 = hs + (4 * p + 0) * HST;
        const float* h1 = hs + (4 * p + 1) * HST;
        const float* h2 = hs + (4 * p + 2) * HST;
        const float* h3 = hs + (4 * p + 3) * HST;
        __half* arow = Anext + (size_t)pg * KA;
        int c0 = g * 8;
        __half lh[8], ll[8], rh[8], rl[8];
#pragma unroll
        for (int j = 0; j < 8; j++) {
            float a = h0[c0 + j], b = h1[c0 + j], c = h2[c0 + j], d = h3[c0 + j];
            float lv = a + (2.f/3.f) * b + (1.f/3.f) * c;
            float rv = (1.f/3.f) * b + (2.f/3.f) * c + d;
            split_fp16(lv, lh[j], ll[j]);
            split_fp16(rv, rh[j], rl[j]);
        }
        int cL = bn + c0;
        *(uint4*)(arow + cL) = *(const uint4*)lh;
        *(uint4*)(arow + 512 + cL) = *(const uint4*)ll;
        *(uint4*)(arow + 256 + cL) = *(const uint4*)rh;
        *(uint4*)(arow + 768 + cL) = *(const uint4*)rl;
    }
}

// ---------------- split-K partial GEMM (l=6..4) ----------------
__global__ void __launch_bounds__(NTHR, 2)
gemm_partial_kernel(const __half* __restrict__ A,
                    const __half* __restrict__ B,
                    float* __restrict__ P, int M, int cnt) {
    extern __shared__ __align__(128) char smem[];
    const uint32_t sbase = smem_u32(smem);
    const int tid = threadIdx.x;
    const int wid = tid >> 5;
    const int lid = tid & 31;
    const int bn = blockIdx.x * 128;
    const int bm = blockIdx.y * 128;
    const int c0 = blockIdx.z * cnt;

    const char* Ab = (const char*)A + (size_t)bm * ROWA;
    const char* Bb = (const char*)B + (size_t)bn * ROWBB;
    float* Pb = P + ((size_t)blockIdx.z * M + bm) * D + bn;

    float acc[2][4][4];
#pragma unroll
    for (int mf = 0; mf < 2; mf++)
#pragma unroll
        for (int nf = 0; nf < 4; nf++)
#pragma unroll
            for (int q = 0; q < 4; q++) acc[mf][nf][q] = 0.0f;

    const int wm = (wid & 3) * 32;
    const int wn = (wid >> 2) * 32;
    const uint32_t aOff = (uint32_t)(wm + (lid & 7) + ((lid & 8) ? 8 : 0)) * SROW +
                          ((lid & 16) ? 16 : 0);
    const uint32_t bOff = (uint32_t)(wn + (lid & 7) + ((lid & 16) ? 8 : 0)) * SROW +
                          ((lid & 8) ? 16 : 0);

    load_stage_g(sbase, 0, c0, Ab, Bb, tid);
    if (cnt > 1) load_stage_g(sbase, 1, c0 + 1, Ab, Bb, tid);

    for (int i = 0; i < cnt; i++) {
        if (i + 2 < cnt) {
            asm volatile("cp.async.wait_group 1;" ::: "memory");
        } else {
            asm volatile("cp.async.wait_group 0;" ::: "memory");
        }
        __syncthreads();
        if (i + 2 < cnt)
            load_stage_g(sbase, (i + 2) % NSTAGE, c0 + i + 2, Ab, Bb, tid);

        uint32_t sA = sbase + (i % NSTAGE) * STAGE;
        compute_chunk(sA + aOff, sA + TILE_B + bOff, acc);
    }

#pragma unroll
    for (int mf = 0; mf < 2; mf++) {
#pragma unroll
        for (int half = 0; half < 2; half++) {
            int r = wm + mf * 16 + (lid >> 2) + half * 8;
            float* prow = Pb + (size_t)r * D + wn;
#pragma unroll
            for (int nf = 0; nf < 4; nf++) {
                int col = nf * 8 + 2 * (lid & 3);
                float2 o;
                o.x = acc[mf][nf][half * 2 + 0];
                o.y = acc[mf][nf][half * 2 + 1];
                *(float2*)(prow + col) = o;
            }
        }
    }
}

// ---------------- epilogue: sum splits + bias + tanh + combine + split ----------------
__global__ void __launch_bounds__(256)
epilogue_combine_kernel(const float* __restrict__ P, int S,
                        const float* __restrict__ bias,
                        __half* __restrict__ Anext,
                        float* __restrict__ hout, int M) {
    int idx = blockIdx.x * blockDim.x + threadIdx.x;
    int nPar = M >> 2;
    if (idx >= nPar * 64) return;
    int p = idx >> 6;
    int q = idx & 63;

    float4 h[4];
#pragma unroll
    for (int j = 0; j < 4; j++) {
        int row = 4 * p + j;
        float4 sum = *(const float4*)(P + (size_t)row * D + q * 4);
        for (int s = 1; s < S; s++) {
            float4 t = *(const float4*)(P + ((size_t)s * M + row) * D + q * 4);
            sum.x += t.x; sum.y += t.y; sum.z += t.z; sum.w += t.w;
        }
        float4 bv = *(const float4*)(bias + (size_t)row * D + q * 4);
        h[j].x = tanhf(sum.x + bv.x);
        h[j].y = tanhf(sum.y + bv.y);
        h[j].z = tanhf(sum.z + bv.z);
        h[j].w = tanhf(sum.w + bv.w);
        if (hout) *(float4*)(hout + (size_t)row * D + q * 4) = h[j];
    }

    if (Anext) {
        float4 uL, uR;
        uL.x = h[0].x + (2.f/3.f) * h[1].x + (1.f/3.f) * h[2].x;
        uL.y = h[0].y + (2.f/3.f) * h[1].y + (1.f/3.f) * h[2].y;
        uL.z = h[0].z + (2.f/3.f) * h[1].z + (1.f/3.f) * h[2].z;
        uL.w = h[0].w + (2.f/3.f) * h[1].w + (1.f/3.f) * h[2].w;
        uR.x = (1.f/3.f) * h[1].x + (2.f/3.f) * h[2].x + h[3].x;
        uR.y = (1.f/3.f) * h[1].y + (2.f/3.f) * h[2].y + h[3].y;
        uR.z = (1.f/3.f) * h[1].z + (2.f/3.f) * h[2].z + h[3].z;
        uR.w = (1.f/3.f) * h[1].w + (2.f/3.f) * h[2].w + h[3].w;

        __half lh[4], ll[4], rh[4], rl[4];
        split_fp16(uL.x, lh[0], ll[0]);
        split_fp16(uL.y, lh[1], ll[1]);
        split_fp16(uL.z, lh[2], ll[2]);
        split_fp16(uL.w, lh[3], ll[3]);
        split_fp16(uR.x, rh[0], rl[0]);
        split_fp16(uR.y, rh[1], rl[1]);
        split_fp16(uR.z, rh[2], rl[2]);
        split_fp16(uR.w, rh[3], rl[3]);

        __half* arow = Anext + (size_t)p * KA + q * 4;
        *(uint2*)(arow)       = *(const uint2*)lh;
        *(uint2*)(arow + 256) = *(const uint2*)rh;
        *(uint2*)(arow + 512) = *(const uint2*)ll;
        *(uint2*)(arow + 768) = *(const uint2*)rl;
    }
}

// ---------------- small levels (M<=64): fp32 warp-per-output ----------------
__global__ void __launch_bounds__(256)
small_level_kernel(const float* __restrict__ hprev,
                   const float* __restrict__ Wl,
                   const float* __restrict__ Wr,
                   const float* __restrict__ bias,
                   float* __restrict__ hout, int Mout) {
    int gw = (blockIdx.x * blockDim.x + threadIdx.x) >> 5;
    int lid = threadIdx.x & 31;
    if (gw >= Mout * D) return;
    int p = gw >> 8;
    int n = gw & 255;
    const float* h0 = hprev + (size_t)(4 * p) * D;
    const float* wl = Wl + (size_t)n * D;
    const float* wr = Wr + (size_t)n * D;
    float acc = 0.f;
#pragma unroll
    for (int i = 0; i < 8; i++) {
        int k = lid + i * 32;
        float a = h0[k], b = h0[D + k], c = h0[2 * D + k], d = h0[3 * D + k];
        float uL = a + (2.f/3.f) * b + (1.f/3.f) * c;
        float uR = (1.f/3.f) * b + (2.f/3.f) * c + d;
        acc = fmaf(uL, wl[k], acc);
        acc = fmaf(uR, wr[k], acc);
    }
#pragma unroll
    for (int o = 16; o; o >>= 1) acc += __shfl_xor_sync(0xffffffffu, acc, o);
    if (lid == 0)
        hout[(size_t)p * D + n] = tanhf(acc + bias[(size_t)p * D + n]);
}

// ---------------- launcher ----------------
extern "C" void kernel_launch(void* const* d_in, const int* in_sizes, int n_in,
                              void* d_out, int out_size) {
    const float* vectors = (const float*)d_in[0];
    const float* Wl = (const float*)d_in[1];
    const float* Wr = (const float*)d_in[2];
    float* out = (float*)d_out;

    __half *Acat0, *Acat1, *Bcat;
    float *part, *hsA, *hsB;
    cudaGetSymbolAddress((void**)&Acat0, g_Acat0);
    cudaGetSymbolAddress((void**)&Acat1, g_Acat1);
    cudaGetSymbolAddress((void**)&Bcat, g_Bcat);
    cudaGetSymbolAddress((void**)&part, g_part);
    cudaGetSymbolAddress((void**)&hsA, g_hsA);
    cudaGetSymbolAddress((void**)&hsB, g_hsB);

    cudaFuncSetAttribute(gemm_fused_l7,
                         cudaFuncAttributeMaxDynamicSharedMemorySize, SMEM_TOTAL);
    cudaFuncSetAttribute(gemm_fused_l7,
                         cudaFuncAttributePreferredSharedMemoryCarveout, 100);
    cudaFuncSetAttribute(gemm_partial_kernel,
                         cudaFuncAttributeMaxDynamicSharedMemorySize, SMEM_TOTAL);
    cudaFuncSetAttribute(gemm_partial_kernel,
                         cudaFuncAttributePreferredSharedMemoryCarveout, 100);

    prep_w_kernel<<<(D * 512 + 255) / 256, 256>>>(Wl, Wr, Bcat);

    static const int offs[9] = {0, 1, 5, 21, 85, 341, 1365, 5461, 21845};

    const float* leaves = vectors + (size_t)offs[8] * D;
    leaf_reduce_kernel<<<(16384 * 128 + 255) / 256, 256>>>(leaves, Acat0, 16384);

    // l=7: fused full-K GEMM, Acat0 -> Acat1
    {
        dim3 grid(2, 128);
        gemm_fused_l7<<<grid, NTHR, SMEM_TOTAL>>>(
            Acat0, Bcat, vectors + (size_t)offs[7] * D, Acat1, 16384);
    }

    // l=6..4: split-K (S * cnt = 16)
    static const int SPLITS[8] = {0, 0, 0, 0, 16, 8, 4, 0};
    __half* Ain = Acat1;
    for (int l = 6; l >= 4; --l) {
        int M = 1 << (2 * l);
        int S = SPLITS[l];
        int cnt = NCHUNK / S;
        __half* Anext =
            (l > 4) ? ((Ain == Acat0) ? Acat1 : Acat0) : (__half*)nullptr;
        float* hout = (l == 4) ? hsA : nullptr;
        const float* bias = vectors + (size_t)offs[l] * D;

        dim3 grid(2, M / 128, S);
        gemm_partial_kernel<<<grid, NTHR, SMEM_TOTAL>>>(Ain, Bcat, part, M, cnt);

        int nthr = (M / 4) * 64;
        epilogue_combine_kernel<<<(nthr + 255) / 256, 256>>>(part, S, bias, Anext, hout, M);

        Ain = Anext;
    }

    // l=3..0: fp32 SIMT
    const float* hin = hsA;
    for (int l = 3; l >= 0; --l) {
        int M = 1 << (2 * l);
        float* hout = (l == 0) ? out : ((l & 1) ? hsB : hsA);
        const float* bias = vectors + (size_t)offs[l] * D;
        int nwarps = M * D;
        small_level_kernel<<<(nwarps * 32 + 255) / 256, 256>>>(hin, Wl, Wr, bias, hout, M);
        hin = hout;
    }
}